// round 3
// baseline (speedup 1.0000x reference)
#include <cuda_runtime.h>

// Problem constants
#define SEQL   1024
#define DMODEL 1024
#define NBATCH 4
#define NHEADS 16
#define DEPTH  64
#define NHTOT  (NBATCH * NHEADS)   // 64
#define NLROWS (NBATCH * SEQL)     // 4096
#define QROWS  (NHTOT * SEQL)      // 65536

// Scratch (device globals; allocation-free per harness rules)
__device__ float g_Q[QROWS * DEPTH];
__device__ float g_K[QROWS * DEPTH];
__device__ float g_V[QROWS * DEPTH];
__device__ float g_QE[(size_t)QROWS * SEQL];   // 268 MB, upper-triangular-ish region used
__device__ float g_AO[NLROWS * DMODEL];

// ---------------------------------------------------------------------------
// Generic GEMM:  out = (X[M,1024] @ W[1024,1024] + bias) * scale
// headmode=1: write in per-head layout out[((n*16+h)*1024+l)*64+dd]
// headmode=0: natural row-major out[row*1024+col]
// BM=128, BN=64, BK=16, 256 threads, 8x4 micro-tile per thread.
// ---------------------------------------------------------------------------
__global__ __launch_bounds__(256) void ra_proj_kernel(
    const float* __restrict__ X, const float* __restrict__ W,
    const float* __restrict__ bias, float* __restrict__ out,
    float scale, int headmode)
{
    __shared__ __align__(16) float AsT[16][132];   // [k][r] transposed
    __shared__ __align__(16) float Bs[16][68];     // [k][c]

    const int t    = threadIdx.x;
    const int row0 = blockIdx.y * 128;
    const int col0 = blockIdx.x * 64;
    const int ty   = t >> 4, tx = t & 15;
    const int ra   = ty * 4;          // rows ra..ra+3 and ra+64..ra+67
    const int ccc  = tx * 4;          // cols ccc..ccc+3 (within tile)

    const int lr  = t >> 1;           // A load row 0..127
    const int lk  = (t & 1) * 8;      // A load k offset 0 or 8
    const int bkr = t >> 4;           // B load row 0..15
    const int bkc = (t & 15) * 4;     // B load col

    float acc[2][4][4];
    #pragma unroll
    for (int g = 0; g < 2; g++)
        #pragma unroll
        for (int i = 0; i < 4; i++)
            #pragma unroll
            for (int j = 0; j < 4; j++) acc[g][i][j] = 0.f;

    for (int k0 = 0; k0 < DMODEL; k0 += 16) {
        float4 a0 = *(const float4*)(X + (size_t)(row0 + lr) * DMODEL + k0 + lk);
        float4 a1 = *(const float4*)(X + (size_t)(row0 + lr) * DMODEL + k0 + lk + 4);
        AsT[lk + 0][lr] = a0.x; AsT[lk + 1][lr] = a0.y;
        AsT[lk + 2][lr] = a0.z; AsT[lk + 3][lr] = a0.w;
        AsT[lk + 4][lr] = a1.x; AsT[lk + 5][lr] = a1.y;
        AsT[lk + 6][lr] = a1.z; AsT[lk + 7][lr] = a1.w;
        *(float4*)&Bs[bkr][bkc] =
            *(const float4*)(W + (size_t)(k0 + bkr) * DMODEL + col0 + bkc);
        __syncthreads();

        #pragma unroll
        for (int kk = 0; kk < 16; kk++) {
            float4 av0 = *(const float4*)&AsT[kk][ra];
            float4 av1 = *(const float4*)&AsT[kk][ra + 64];
            float4 bv  = *(const float4*)&Bs[kk][ccc];
            float a0r[4] = {av0.x, av0.y, av0.z, av0.w};
            float a1r[4] = {av1.x, av1.y, av1.z, av1.w};
            float br[4]  = {bv.x, bv.y, bv.z, bv.w};
            #pragma unroll
            for (int i = 0; i < 4; i++) {
                #pragma unroll
                for (int j = 0; j < 4; j++) {
                    acc[0][i][j] += a0r[i] * br[j];
                    acc[1][i][j] += a1r[i] * br[j];
                }
            }
        }
        __syncthreads();
    }

    float bv4[4];
    #pragma unroll
    for (int j = 0; j < 4; j++) bv4[j] = bias[col0 + ccc + j];
    const int h = col0 >> 6;

    #pragma unroll
    for (int g = 0; g < 2; g++) {
        #pragma unroll
        for (int i2 = 0; i2 < 4; i2++) {
            const int row = row0 + g * 64 + ra + i2;
            size_t idx;
            if (headmode) {
                const int n = row >> 10;
                const int l = row & 1023;
                idx = ((size_t)((n * NHEADS + h) * SEQL + l)) * DEPTH + ccc;
            } else {
                idx = (size_t)row * DMODEL + col0 + ccc;
            }
            float4 w;
            w.x = (acc[g][i2][0] + bv4[0]) * scale;
            w.y = (acc[g][i2][1] + bv4[1]) * scale;
            w.z = (acc[g][i2][2] + bv4[2]) * scale;
            w.w = (acc[g][i2][3] + bv4[3]) * scale;
            *(float4*)(out + idx) = w;
        }
    }
}

// ---------------------------------------------------------------------------
// QE GEMM: QE[r, m] = sum_dd Q[r, dd] * E[m, dd],  E = pos_emb[1024 + m]
// r in head layout (nh*1024 + i). Skips tiles never read by attention
// (attention reads m >= L-1-i only).
// ---------------------------------------------------------------------------
__global__ __launch_bounds__(256) void ra_qe_kernel(
    const float* __restrict__ Q, const float* __restrict__ pos_emb,
    float* __restrict__ QEo)
{
    const int m0 = blockIdx.x * 64;
    const int r0 = blockIdx.y * 64;
    const int i0 = r0 & (SEQL - 1);
    if (m0 + 63 < SEQL - 64 - i0) return;   // tile entirely unused

    __shared__ __align__(16) float QtT[64 * 64];
    __shared__ __align__(16) float EtT[64 * 64];

    const int t    = threadIdx.x;
    const int lrow = t >> 2;
    const int ld0  = (t & 3) * 16;

    #pragma unroll
    for (int u = 0; u < 4; u++) {
        float4 a = *(const float4*)(Q + (size_t)(r0 + lrow) * DEPTH + ld0 + u * 4);
        QtT[(ld0 + u * 4 + 0) * 64 + lrow] = a.x;
        QtT[(ld0 + u * 4 + 1) * 64 + lrow] = a.y;
        QtT[(ld0 + u * 4 + 2) * 64 + lrow] = a.z;
        QtT[(ld0 + u * 4 + 3) * 64 + lrow] = a.w;
        float4 e = *(const float4*)(pos_emb + (size_t)(1024 + m0 + lrow) * DEPTH + ld0 + u * 4);
        EtT[(ld0 + u * 4 + 0) * 64 + lrow] = e.x;
        EtT[(ld0 + u * 4 + 1) * 64 + lrow] = e.y;
        EtT[(ld0 + u * 4 + 2) * 64 + lrow] = e.z;
        EtT[(ld0 + u * 4 + 3) * 64 + lrow] = e.w;
    }
    __syncthreads();

    const int ty = t >> 4, tx = t & 15;
    const int rr0 = ty * 4, cc0 = tx * 4;
    float acc[4][4];
    #pragma unroll
    for (int i = 0; i < 4; i++)
        #pragma unroll
        for (int j = 0; j < 4; j++) acc[i][j] = 0.f;

    #pragma unroll 8
    for (int dd = 0; dd < 64; dd++) {
        float4 a = *(const float4*)&QtT[dd * 64 + rr0];
        float4 b = *(const float4*)&EtT[dd * 64 + cc0];
        float av[4] = {a.x, a.y, a.z, a.w};
        float bv[4] = {b.x, b.y, b.z, b.w};
        #pragma unroll
        for (int i = 0; i < 4; i++)
            #pragma unroll
            for (int j = 0; j < 4; j++) acc[i][j] += av[i] * bv[j];
    }

    #pragma unroll
    for (int rr = 0; rr < 4; rr++) {
        float4 w = make_float4(acc[rr][0], acc[rr][1], acc[rr][2], acc[rr][3]);
        *(float4*)(QEo + (size_t)(r0 + rr0 + rr) * SEQL + m0 + cc0) = w;
    }
}

// ---------------------------------------------------------------------------
// Flash-style causal attention with relative bias gather.
// Block = (query tile of 64, one (n,h)). 256 threads, 4x4 micro-tiles.
// logits = q·k + QE[i, L-1-i+j]  (q pre-scaled by 1/sqrt(d)); j>i masked.
// Static smem = exactly 48 KB (no opt-in attribute needed).
// ---------------------------------------------------------------------------
__global__ __launch_bounds__(256) void ra_attn_kernel(
    const float* __restrict__ Q, const float* __restrict__ K,
    const float* __restrict__ V, const float* __restrict__ QE,
    float* __restrict__ AO)
{
    __shared__ __align__(16) float QsT[64 * 64];  // [dd][r]
    __shared__ __align__(16) float KVs[64 * 64];  // K transposed [dd][j], then V natural [j][c]
    __shared__ __align__(16) float Ps[64 * 64];   // [r][j]

    const int nh = blockIdx.y;
    const int i0 = blockIdx.x * 64;
    const int t  = threadIdx.x;
    const int ty = t >> 4, tx = t & 15;
    const int rr0 = ty * 4, cc0 = tx * 4;
    const int lrow = t >> 2;
    const int ld0  = (t & 3) * 16;

    // Load Q tile transposed
    const float* qbase = Q + (size_t)(nh * SEQL + i0) * DEPTH;
    #pragma unroll
    for (int u = 0; u < 4; u++) {
        float4 v = *(const float4*)(qbase + lrow * DEPTH + ld0 + u * 4);
        QsT[(ld0 + u * 4 + 0) * 64 + lrow] = v.x;
        QsT[(ld0 + u * 4 + 1) * 64 + lrow] = v.y;
        QsT[(ld0 + u * 4 + 2) * 64 + lrow] = v.z;
        QsT[(ld0 + u * 4 + 3) * 64 + lrow] = v.w;
    }

    float o[4][4];
    #pragma unroll
    for (int i = 0; i < 4; i++)
        #pragma unroll
        for (int j = 0; j < 4; j++) o[i][j] = 0.f;
    float rm[4] = {-1e30f, -1e30f, -1e30f, -1e30f};
    float rl[4] = {0.f, 0.f, 0.f, 0.f};

    for (int j0 = 0; j0 <= i0; j0 += 64) {
        __syncthreads();   // prev-iter PV done (and QsT ready on iter 0)

        // Load K tile transposed into KVs
        const float* kbase = K + (size_t)(nh * SEQL + j0) * DEPTH;
        #pragma unroll
        for (int u = 0; u < 4; u++) {
            float4 v = *(const float4*)(kbase + lrow * DEPTH + ld0 + u * 4);
            KVs[(ld0 + u * 4 + 0) * 64 + lrow] = v.x;
            KVs[(ld0 + u * 4 + 1) * 64 + lrow] = v.y;
            KVs[(ld0 + u * 4 + 2) * 64 + lrow] = v.z;
            KVs[(ld0 + u * 4 + 3) * 64 + lrow] = v.w;
        }
        __syncthreads();

        // Scores: S = Q @ K^T (q already scaled by 1/8)
        float s[4][4];
        #pragma unroll
        for (int i = 0; i < 4; i++)
            #pragma unroll
            for (int j = 0; j < 4; j++) s[i][j] = 0.f;
        #pragma unroll 8
        for (int dd = 0; dd < 64; dd++) {
            float4 a = *(const float4*)&QsT[dd * 64 + rr0];
            float4 b = *(const float4*)&KVs[dd * 64 + cc0];
            float av[4] = {a.x, a.y, a.z, a.w};
            float bv[4] = {b.x, b.y, b.z, b.w};
            #pragma unroll
            for (int i = 0; i < 4; i++)
                #pragma unroll
                for (int j = 0; j < 4; j++) s[i][j] += av[i] * bv[j];
        }

        // Relative bias gather + causal mask
        #pragma unroll
        for (int rr = 0; rr < 4; rr++) {
            const int i = i0 + rr0 + rr;
            const float* qerow = QE + (size_t)(nh * SEQL + i) * SEQL
                                    + (SEQL - 1 - i + j0 + cc0);
            #pragma unroll
            for (int cc = 0; cc < 4; cc++) {
                const int j = j0 + cc0 + cc;
                if (j <= i) s[rr][cc] += qerow[cc];
                else        s[rr][cc] = -1e30f;
            }
        }

        // Online softmax (16 threads per row group; lanes 0-15 / 16-31)
        #pragma unroll
        for (int rr = 0; rr < 4; rr++) {
            float mx = fmaxf(fmaxf(s[rr][0], s[rr][1]), fmaxf(s[rr][2], s[rr][3]));
            #pragma unroll
            for (int off = 1; off < 16; off <<= 1)
                mx = fmaxf(mx, __shfl_xor_sync(0xffffffffu, mx, off));
            const float mnew  = fmaxf(rm[rr], mx);
            const float alpha = __expf(rm[rr] - mnew);
            float psum = 0.f;
            #pragma unroll
            for (int cc = 0; cc < 4; cc++) {
                const float p = __expf(s[rr][cc] - mnew);
                Ps[(rr0 + rr) * 64 + cc0 + cc] = p;
                psum += p;
            }
            #pragma unroll
            for (int off = 1; off < 16; off <<= 1)
                psum += __shfl_xor_sync(0xffffffffu, psum, off);
            rl[rr] = rl[rr] * alpha + psum;
            rm[rr] = mnew;
            #pragma unroll
            for (int cc = 0; cc < 4; cc++) o[rr][cc] *= alpha;
        }
        __syncthreads();   // Ps complete; KVs free to be overwritten

        // Load V tile (natural layout) into KVs
        const float* vbase = V + (size_t)(nh * SEQL + j0) * DEPTH;
        #pragma unroll
        for (int u = 0; u < 4; u++) {
            float4 v = *(const float4*)(vbase + lrow * DEPTH + ld0 + u * 4);
            *(float4*)&KVs[lrow * 64 + ld0 + u * 4] = v;
        }
        __syncthreads();

        // O += P @ V
        #pragma unroll 4
        for (int j = 0; j < 64; j += 4) {
            float4 pa[4];
            #pragma unroll
            for (int rr = 0; rr < 4; rr++)
                pa[rr] = *(const float4*)&Ps[(rr0 + rr) * 64 + j];
            float4 vb[4];
            #pragma unroll
            for (int jj = 0; jj < 4; jj++)
                vb[jj] = *(const float4*)&KVs[(j + jj) * 64 + cc0];
            #pragma unroll
            for (int rr = 0; rr < 4; rr++) {
                const float pv[4] = {pa[rr].x, pa[rr].y, pa[rr].z, pa[rr].w};
                #pragma unroll
                for (int jj = 0; jj < 4; jj++) {
                    o[rr][0] += pv[jj] * vb[jj].x;
                    o[rr][1] += pv[jj] * vb[jj].y;
                    o[rr][2] += pv[jj] * vb[jj].z;
                    o[rr][3] += pv[jj] * vb[jj].w;
                }
            }
        }
    }

    // Epilogue: normalize and write back in [N, L, D_MODEL] layout
    const int n = nh >> 4, h = nh & 15;
    #pragma unroll
    for (int rr = 0; rr < 4; rr++) {
        const int i = i0 + rr0 + rr;
        const float inv = 1.f / rl[rr];
        float4 w = make_float4(o[rr][0] * inv, o[rr][1] * inv,
                               o[rr][2] * inv, o[rr][3] * inv);
        *(float4*)(AO + (size_t)(n * SEQL + i) * DMODEL + h * DEPTH + cc0) = w;
    }
}

// ---------------------------------------------------------------------------
extern "C" void kernel_launch(void* const* d_in, const int* in_sizes, int n_in,
                              void* d_out, int out_size)
{
    (void)in_sizes; (void)n_in; (void)out_size;
    const float* q_in    = (const float*)d_in[0];
    const float* k_in    = (const float*)d_in[1];
    const float* v_in    = (const float*)d_in[2];
    /* d_in[3] = mask (triu k=1) — handled analytically */
    const float* Wq      = (const float*)d_in[4];
    const float* bq      = (const float*)d_in[5];
    const float* Wk      = (const float*)d_in[6];
    const float* bk      = (const float*)d_in[7];
    const float* Wv      = (const float*)d_in[8];
    const float* bv      = (const float*)d_in[9];
    const float* Wo      = (const float*)d_in[10];
    const float* bo      = (const float*)d_in[11];
    const float* pos_emb = (const float*)d_in[12];

    float *Qp, *Kp, *Vp, *QEp, *AOp;
    cudaGetSymbolAddress((void**)&Qp,  g_Q);
    cudaGetSymbolAddress((void**)&Kp,  g_K);
    cudaGetSymbolAddress((void**)&Vp,  g_V);
    cudaGetSymbolAddress((void**)&QEp, g_QE);
    cudaGetSymbolAddress((void**)&AOp, g_AO);

    const dim3 gproj(DMODEL / 64, NLROWS / 128);   // (16, 32)

    // Q projection carries the 1/sqrt(d) scale so q·k and q·e are both scaled.
    ra_proj_kernel<<<gproj, 256>>>(q_in, Wq, bq, Qp, 0.125f, 1);
    ra_proj_kernel<<<gproj, 256>>>(k_in, Wk, bk, Kp, 1.0f, 1);
    ra_proj_kernel<<<gproj, 256>>>(v_in, Wv, bv, Vp, 1.0f, 1);

    ra_qe_kernel<<<dim3(SEQL / 64, QROWS / 64), 256>>>(Qp, pos_emb, QEp);

    ra_attn_kernel<<<dim3(SEQL / 64, NHTOT), 256>>>(Qp, Kp, Vp, QEp, AOp);

    ra_proj_kernel<<<gproj, 256>>>(AOp, Wo, bo, (float*)d_out, 1.0f, 0);
}

// round 5
// speedup vs baseline: 1.6160x; 1.6160x over previous
#include <cuda_runtime.h>
#include <cuda_bf16.h>
#include <cstdint>

// Problem constants
#define SEQL   1024
#define DMODEL 1024
#define NBATCH 4
#define NHEADS 16
#define DEPTH  64
#define NHTOT  (NBATCH * NHEADS)   // 64
#define NLROWS (NBATCH * SEQL)     // 4096
#define QROWS  (NHTOT * SEQL)      // 65536

// Scratch (device globals; allocation-free per harness rules)
__device__ __align__(128) float g_Q[QROWS * DEPTH];
__device__ __align__(128) float g_K[QROWS * DEPTH];
__device__ __align__(128) float g_V[QROWS * DEPTH];
__device__ __align__(128) float g_QE[(size_t)QROWS * SEQL];   // 268 MB (band used)
__device__ __align__(128) float g_AO[NLROWS * DMODEL];
// bf16 hi/lo split buffers (raw u16 storage)
__device__ __align__(128) unsigned short g_Ahi[NLROWS * DMODEL];
__device__ __align__(128) unsigned short g_Alo[NLROWS * DMODEL];
__device__ __align__(128) unsigned short g_Bhi[DMODEL * DMODEL];
__device__ __align__(128) unsigned short g_Blo[DMODEL * DMODEL];
__device__ float g_zbias[DMODEL];   // zero-initialized

// ---------------------------------------------------------------------------
// Split-bf16 conversion kernels
// ---------------------------------------------------------------------------
__global__ __launch_bounds__(256) void ra_conv_hilo(
    const float* __restrict__ x, unsigned short* __restrict__ hi,
    unsigned short* __restrict__ lo, int n4)
{
    int i = blockIdx.x * 256 + threadIdx.x;
    if (i >= n4) return;
    float4 v = ((const float4*)x)[i];
    float f[4] = {v.x, v.y, v.z, v.w};
    unsigned short hs[4], ls[4];
    #pragma unroll
    for (int j = 0; j < 4; j++) {
        __nv_bfloat16 hb = __float2bfloat16(f[j]);
        __nv_bfloat16 lb = __float2bfloat16(f[j] - __bfloat162float(hb));
        hs[j] = __bfloat16_as_ushort(hb);
        ls[j] = __bfloat16_as_ushort(lb);
    }
    ((ushort4*)hi)[i] = make_ushort4(hs[0], hs[1], hs[2], hs[3]);
    ((ushort4*)lo)[i] = make_ushort4(ls[0], ls[1], ls[2], ls[3]);
}

// W [K=1024, N=1024] -> W^T hi/lo bf16 [N, K]
__global__ __launch_bounds__(256) void ra_conv_wt(
    const float* __restrict__ W, unsigned short* __restrict__ hiT,
    unsigned short* __restrict__ loT)
{
    __shared__ float tile[32][33];
    const int nx = blockIdx.x * 32 + threadIdx.x;
    const int k0 = blockIdx.y * 32;
    #pragma unroll
    for (int r = 0; r < 4; r++)
        tile[threadIdx.y + r * 8][threadIdx.x] =
            W[(size_t)(k0 + threadIdx.y + r * 8) * DMODEL + nx];
    __syncthreads();
    const int kx = k0 + threadIdx.x;
    const int n0 = blockIdx.x * 32;
    #pragma unroll
    for (int r = 0; r < 4; r++) {
        float v = tile[threadIdx.x][threadIdx.y + r * 8];
        __nv_bfloat16 hb = __float2bfloat16(v);
        __nv_bfloat16 lb = __float2bfloat16(v - __bfloat162float(hb));
        size_t o = (size_t)(n0 + threadIdx.y + r * 8) * DMODEL + kx;
        hiT[o] = __bfloat16_as_ushort(hb);
        loT[o] = __bfloat16_as_ushort(lb);
    }
}

// ---------------------------------------------------------------------------
// mma.sync split-bf16 GEMM: out[M,N] = (Ahi+Alo)[M,KT] @ (Bhi+Blo)[N,KT]^T
// Block tile 128x128, K-chunk 32, 8 warps (32x64 each), double-buffered smem.
// 3 MMAs per fragment pair: hi*hi + hi*lo + lo*hi (split-bf16 ~= fp32).
// ---------------------------------------------------------------------------
#define PITCH   40                       // bf16 elements per smem row (32 + 8 pad)
#define A_HI_O  0
#define A_LO_O  (128 * PITCH)            // 5120
#define B_HI_O  (2 * 128 * PITCH)        // 10240
#define B_LO_O  (3 * 128 * PITCH)        // 15360
#define STAGE_E (4 * 128 * PITCH)        // 20480 elements
#define SMEM_DYN (2 * STAGE_E * 2)       // 81920 bytes

__device__ __forceinline__ uint32_t lds_u32(const unsigned short* p) {
    return *(const uint32_t*)p;
}
#define MMA_BF16(c, a, b) \
    asm volatile("mma.sync.aligned.m16n8k16.row.col.f32.bf16.bf16.f32 " \
                 "{%0,%1,%2,%3}, {%4,%5,%6,%7}, {%8,%9}, {%0,%1,%2,%3};" \
                 : "+f"((c)[0]), "+f"((c)[1]), "+f"((c)[2]), "+f"((c)[3]) \
                 : "r"((a)[0]), "r"((a)[1]), "r"((a)[2]), "r"((a)[3]), \
                   "r"((b)[0]), "r"((b)[1]))

__global__ __launch_bounds__(256) void ra_mma_gemm(
    const unsigned short* __restrict__ Ahi, const unsigned short* __restrict__ Alo,
    const unsigned short* __restrict__ Bhi, const unsigned short* __restrict__ Blo,
    const float* __restrict__ bias, float* __restrict__ out,
    int KT, float scale, int headmode, int qe_mode)
{
    const int m0 = blockIdx.y * 128;
    const int n0 = blockIdx.x * 128;
    if (qe_mode) {
        const int i0 = m0 & (SEQL - 1);
        if (n0 + 127 < (SEQL - 128) - i0) return;   // tile never read by attention
    }
    extern __shared__ unsigned short sm[];

    const int tid    = threadIdx.x;
    const int wid    = tid >> 5;
    const int lane   = tid & 31;
    const int warp_m = wid & 3;       // 0..3 -> 32-row strip
    const int warp_n = wid >> 2;      // 0..1 -> 64-col strip

    // global->smem load map: thread t handles row t>>1, 16-elem half (t&1)
    const int glr = tid >> 1;
    const int glc = (tid & 1) * 16;
    const size_t a_off = (size_t)(m0 + glr) * KT + glc;
    const size_t b_off = (size_t)(n0 + glr) * KT + glc;
    const int    s_off = glr * PITCH + glc;

    float acc[2][8][4];
    #pragma unroll
    for (int mt = 0; mt < 2; mt++)
        #pragma unroll
        for (int nt = 0; nt < 8; nt++)
            #pragma unroll
            for (int i = 0; i < 4; i++) acc[mt][nt][i] = 0.f;

    const int nch = KT >> 5;   // K-chunks of 32

    // preload chunk 0 into stage 0
    {
        #pragma unroll
        for (int u = 0; u < 2; u++) {
            *(uint4*)(sm + A_HI_O + s_off + u * 8) = *(const uint4*)(Ahi + a_off + u * 8);
            *(uint4*)(sm + A_LO_O + s_off + u * 8) = *(const uint4*)(Alo + a_off + u * 8);
            *(uint4*)(sm + B_HI_O + s_off + u * 8) = *(const uint4*)(Bhi + b_off + u * 8);
            *(uint4*)(sm + B_LO_O + s_off + u * 8) = *(const uint4*)(Blo + b_off + u * 8);
        }
    }
    __syncthreads();

    const int fr_a = (lane >> 2);            // fragment row within 8-group
    const int fr_k = (lane & 3) * 2;         // fragment k pair

    for (int c = 0; c < nch; c++) {
        // prefetch chunk c+1 (global -> regs)
        uint4 pf[8];
        if (c + 1 < nch) {
            const size_t ka = a_off + (size_t)(c + 1) * 32;
            const size_t kb = b_off + (size_t)(c + 1) * 32;
            #pragma unroll
            for (int u = 0; u < 2; u++) {
                pf[u * 4 + 0] = *(const uint4*)(Ahi + ka + u * 8);
                pf[u * 4 + 1] = *(const uint4*)(Alo + ka + u * 8);
                pf[u * 4 + 2] = *(const uint4*)(Bhi + kb + u * 8);
                pf[u * 4 + 3] = *(const uint4*)(Blo + kb + u * 8);
            }
        }

        const unsigned short* st = sm + (c & 1) * STAGE_E;
        #pragma unroll
        for (int kk = 0; kk < 32; kk += 16) {
            // A fragments (hi & lo) for both 16-row tiles
            uint32_t ah[2][4], al[2][4];
            #pragma unroll
            for (int mt = 0; mt < 2; mt++) {
                const int r0 = warp_m * 32 + mt * 16 + fr_a;
                const unsigned short* pa = st + A_HI_O + r0 * PITCH + kk + fr_k;
                ah[mt][0] = lds_u32(pa);
                ah[mt][1] = lds_u32(pa + 8 * PITCH);
                ah[mt][2] = lds_u32(pa + 8);
                ah[mt][3] = lds_u32(pa + 8 * PITCH + 8);
                const unsigned short* pl = pa + (A_LO_O - A_HI_O);
                al[mt][0] = lds_u32(pl);
                al[mt][1] = lds_u32(pl + 8 * PITCH);
                al[mt][2] = lds_u32(pl + 8);
                al[mt][3] = lds_u32(pl + 8 * PITCH + 8);
            }
            // B fragments (hi & lo) for 8 n8 tiles
            uint32_t bh[8][2], bl[8][2];
            #pragma unroll
            for (int nt = 0; nt < 8; nt++) {
                const int nr = warp_n * 64 + nt * 8 + fr_a;
                const unsigned short* pb = st + B_HI_O + nr * PITCH + kk + fr_k;
                bh[nt][0] = lds_u32(pb);
                bh[nt][1] = lds_u32(pb + 8);
                const unsigned short* pq = pb + (B_LO_O - B_HI_O);
                bl[nt][0] = lds_u32(pq);
                bl[nt][1] = lds_u32(pq + 8);
            }
            // 3-term split MMAs
            #pragma unroll
            for (int mt = 0; mt < 2; mt++)
                #pragma unroll
                for (int nt = 0; nt < 8; nt++) {
                    MMA_BF16(acc[mt][nt], ah[mt], bh[nt]);
                    MMA_BF16(acc[mt][nt], ah[mt], bl[nt]);
                    MMA_BF16(acc[mt][nt], al[mt], bh[nt]);
                }
        }

        if (c + 1 < nch) {
            unsigned short* nst = sm + ((c + 1) & 1) * STAGE_E;
            #pragma unroll
            for (int u = 0; u < 2; u++) {
                *(uint4*)(nst + A_HI_O + s_off + u * 8) = pf[u * 4 + 0];
                *(uint4*)(nst + A_LO_O + s_off + u * 8) = pf[u * 4 + 1];
                *(uint4*)(nst + B_HI_O + s_off + u * 8) = pf[u * 4 + 2];
                *(uint4*)(nst + B_LO_O + s_off + u * 8) = pf[u * 4 + 3];
            }
            __syncthreads();
        }
    }

    // Epilogue
    const int rbase = m0 + warp_m * 32 + fr_a;
    const int cbase = n0 + warp_n * 64 + (lane & 3) * 2;
    #pragma unroll
    for (int mt = 0; mt < 2; mt++) {
        #pragma unroll
        for (int nt = 0; nt < 8; nt++) {
            const int col = cbase + nt * 8;
            const float b0 = bias[col], b1 = bias[col + 1];
            #pragma unroll
            for (int half = 0; half < 2; half++) {
                const int row = rbase + mt * 16 + half * 8;
                size_t oidx;
                if (headmode) {
                    const int n = row >> 10, l = row & (SEQL - 1);
                    const int h = (col >> 6) & (NHEADS - 1);
                    oidx = ((size_t)((n * NHEADS + h) * SEQL + l)) * DEPTH + (col & 63);
                } else {
                    oidx = (size_t)row * (qe_mode ? SEQL : DMODEL) + col;
                }
                float2 w;
                w.x = (acc[mt][nt][half * 2 + 0] + b0) * scale;
                w.y = (acc[mt][nt][half * 2 + 1] + b1) * scale;
                *(float2*)(out + oidx) = w;
            }
        }
    }
}

// ---------------------------------------------------------------------------
// Flash-style causal attention with relative bias gather (fp32, unchanged).
// ---------------------------------------------------------------------------
__global__ __launch_bounds__(256) void ra_attn_kernel(
    const float* __restrict__ Q, const float* __restrict__ K,
    const float* __restrict__ V, const float* __restrict__ QE,
    float* __restrict__ AO)
{
    __shared__ __align__(16) float QsT[64 * 64];
    __shared__ __align__(16) float KVs[64 * 64];
    __shared__ __align__(16) float Ps[64 * 64];

    const int nh = blockIdx.y;
    const int i0 = blockIdx.x * 64;
    const int t  = threadIdx.x;
    const int ty = t >> 4, tx = t & 15;
    const int rr0 = ty * 4, cc0 = tx * 4;
    const int lrow = t >> 2;
    const int ld0  = (t & 3) * 16;

    const float* qbase = Q + (size_t)(nh * SEQL + i0) * DEPTH;
    #pragma unroll
    for (int u = 0; u < 4; u++) {
        float4 v = *(const float4*)(qbase + lrow * DEPTH + ld0 + u * 4);
        QsT[(ld0 + u * 4 + 0) * 64 + lrow] = v.x;
        QsT[(ld0 + u * 4 + 1) * 64 + lrow] = v.y;
        QsT[(ld0 + u * 4 + 2) * 64 + lrow] = v.z;
        QsT[(ld0 + u * 4 + 3) * 64 + lrow] = v.w;
    }

    float o[4][4];
    #pragma unroll
    for (int i = 0; i < 4; i++)
        #pragma unroll
        for (int j = 0; j < 4; j++) o[i][j] = 0.f;
    float rm[4] = {-1e30f, -1e30f, -1e30f, -1e30f};
    float rl[4] = {0.f, 0.f, 0.f, 0.f};

    for (int j0 = 0; j0 <= i0; j0 += 64) {
        __syncthreads();

        const float* kbase = K + (size_t)(nh * SEQL + j0) * DEPTH;
        #pragma unroll
        for (int u = 0; u < 4; u++) {
            float4 v = *(const float4*)(kbase + lrow * DEPTH + ld0 + u * 4);
            KVs[(ld0 + u * 4 + 0) * 64 + lrow] = v.x;
            KVs[(ld0 + u * 4 + 1) * 64 + lrow] = v.y;
            KVs[(ld0 + u * 4 + 2) * 64 + lrow] = v.z;
            KVs[(ld0 + u * 4 + 3) * 64 + lrow] = v.w;
        }
        __syncthreads();

        float s[4][4];
        #pragma unroll
        for (int i = 0; i < 4; i++)
            #pragma unroll
            for (int j = 0; j < 4; j++) s[i][j] = 0.f;
        #pragma unroll 8
        for (int dd = 0; dd < 64; dd++) {
            float4 a = *(const float4*)&QsT[dd * 64 + rr0];
            float4 b = *(const float4*)&KVs[dd * 64 + cc0];
            float av[4] = {a.x, a.y, a.z, a.w};
            float bv[4] = {b.x, b.y, b.z, b.w};
            #pragma unroll
            for (int i = 0; i < 4; i++)
                #pragma unroll
                for (int j = 0; j < 4; j++) s[i][j] += av[i] * bv[j];
        }

        #pragma unroll
        for (int rr = 0; rr < 4; rr++) {
            const int i = i0 + rr0 + rr;
            const float* qerow = QE + (size_t)(nh * SEQL + i) * SEQL
                                    + (SEQL - 1 - i + j0 + cc0);
            #pragma unroll
            for (int cc = 0; cc < 4; cc++) {
                const int j = j0 + cc0 + cc;
                if (j <= i) s[rr][cc] += qerow[cc];
                else        s[rr][cc] = -1e30f;
            }
        }

        #pragma unroll
        for (int rr = 0; rr < 4; rr++) {
            float mx = fmaxf(fmaxf(s[rr][0], s[rr][1]), fmaxf(s[rr][2], s[rr][3]));
            #pragma unroll
            for (int off = 1; off < 16; off <<= 1)
                mx = fmaxf(mx, __shfl_xor_sync(0xffffffffu, mx, off));
            const float mnew  = fmaxf(rm[rr], mx);
            const float alpha = __expf(rm[rr] - mnew);
            float psum = 0.f;
            #pragma unroll
            for (int cc = 0; cc < 4; cc++) {
                const float p = __expf(s[rr][cc] - mnew);
                Ps[(rr0 + rr) * 64 + cc0 + cc] = p;
                psum += p;
            }
            #pragma unroll
            for (int off = 1; off < 16; off <<= 1)
                psum += __shfl_xor_sync(0xffffffffu, psum, off);
            rl[rr] = rl[rr] * alpha + psum;
            rm[rr] = mnew;
            #pragma unroll
            for (int cc = 0; cc < 4; cc++) o[rr][cc] *= alpha;
        }
        __syncthreads();

        const float* vbase = V + (size_t)(nh * SEQL + j0) * DEPTH;
        #pragma unroll
        for (int u = 0; u < 4; u++) {
            float4 v = *(const float4*)(vbase + lrow * DEPTH + ld0 + u * 4);
            *(float4*)&KVs[lrow * 64 + ld0 + u * 4] = v;
        }
        __syncthreads();

        #pragma unroll 4
        for (int j = 0; j < 64; j += 4) {
            float4 pa[4];
            #pragma unroll
            for (int rr = 0; rr < 4; rr++)
                pa[rr] = *(const float4*)&Ps[(rr0 + rr) * 64 + j];
            float4 vb[4];
            #pragma unroll
            for (int jj = 0; jj < 4; jj++)
                vb[jj] = *(const float4*)&KVs[(j + jj) * 64 + cc0];
            #pragma unroll
            for (int rr = 0; rr < 4; rr++) {
                const float pv[4] = {pa[rr].x, pa[rr].y, pa[rr].z, pa[rr].w};
                #pragma unroll
                for (int jj = 0; jj < 4; jj++) {
                    o[rr][0] += pv[jj] * vb[jj].x;
                    o[rr][1] += pv[jj] * vb[jj].y;
                    o[rr][2] += pv[jj] * vb[jj].z;
                    o[rr][3] += pv[jj] * vb[jj].w;
                }
            }
        }
    }

    const int n = nh >> 4, h = nh & 15;
    #pragma unroll
    for (int rr = 0; rr < 4; rr++) {
        const int i = i0 + rr0 + rr;
        const float inv = 1.f / rl[rr];
        float4 w = make_float4(o[rr][0] * inv, o[rr][1] * inv,
                               o[rr][2] * inv, o[rr][3] * inv);
        *(float4*)(AO + (size_t)(n * SEQL + i) * DMODEL + h * DEPTH + cc0) = w;
    }
}

// ---------------------------------------------------------------------------
extern "C" void kernel_launch(void* const* d_in, const int* in_sizes, int n_in,
                              void* d_out, int out_size)
{
    (void)in_sizes; (void)n_in; (void)out_size;
    const float* q_in    = (const float*)d_in[0];
    const float* k_in    = (const float*)d_in[1];
    const float* v_in    = (const float*)d_in[2];
    /* d_in[3] = mask (triu k=1) — handled analytically */
    const float* Wq      = (const float*)d_in[4];
    const float* bq      = (const float*)d_in[5];
    const float* Wk      = (const float*)d_in[6];
    const float* bk      = (const float*)d_in[7];
    const float* Wv      = (const float*)d_in[8];
    const float* bv      = (const float*)d_in[9];
    const float* Wo      = (const float*)d_in[10];
    const float* bo      = (const float*)d_in[11];
    const float* pos_emb = (const float*)d_in[12];

    float *Qp, *Kp, *Vp, *QEp, *AOp, *zb;
    unsigned short *Ahi, *Alo, *Bhi, *Blo;
    cudaGetSymbolAddress((void**)&Qp,  g_Q);
    cudaGetSymbolAddress((void**)&Kp,  g_K);
    cudaGetSymbolAddress((void**)&Vp,  g_V);
    cudaGetSymbolAddress((void**)&QEp, g_QE);
    cudaGetSymbolAddress((void**)&AOp, g_AO);
    cudaGetSymbolAddress((void**)&zb,  g_zbias);
    cudaGetSymbolAddress((void**)&Ahi, g_Ahi);
    cudaGetSymbolAddress((void**)&Alo, g_Alo);
    cudaGetSymbolAddress((void**)&Bhi, g_Bhi);
    cudaGetSymbolAddress((void**)&Blo, g_Blo);

    cudaFuncSetAttribute(ra_mma_gemm, cudaFuncAttributeMaxDynamicSharedMemorySize,
                         SMEM_DYN);

    const dim3 gwt(32, 32);
    const dim3 bwt(32, 8);
    const dim3 gproj(DMODEL / 128, NLROWS / 128);  // (8, 32)
    const int  n4x = (NLROWS * DMODEL) / 4;        // 1048576

    // Q projection (scale folds in 1/sqrt(d))
    ra_conv_hilo<<<n4x / 256, 256>>>(q_in, Ahi, Alo, n4x);
    ra_conv_wt<<<gwt, bwt>>>(Wq, Bhi, Blo);
    ra_mma_gemm<<<gproj, 256, SMEM_DYN>>>(Ahi, Alo, Bhi, Blo, bq, Qp,
                                          DMODEL, 0.125f, 1, 0);
    // K projection
    ra_conv_hilo<<<n4x / 256, 256>>>(k_in, Ahi, Alo, n4x);
    ra_conv_wt<<<gwt, bwt>>>(Wk, Bhi, Blo);
    ra_mma_gemm<<<gproj, 256, SMEM_DYN>>>(Ahi, Alo, Bhi, Blo, bk, Kp,
                                          DMODEL, 1.0f, 1, 0);
    // V projection
    ra_conv_hilo<<<n4x / 256, 256>>>(v_in, Ahi, Alo, n4x);
    ra_conv_wt<<<gwt, bwt>>>(Wv, Bhi, Blo);
    ra_mma_gemm<<<gproj, 256, SMEM_DYN>>>(Ahi, Alo, Bhi, Blo, bv, Vp,
                                          DMODEL, 1.0f, 1, 0);

    // QE = Q @ E^T  (A = Q[65536x64], B = E[1024x64], K=64, band-skipped)
    ra_conv_hilo<<<n4x / 256, 256>>>(Qp, Ahi, Alo, n4x);
    ra_conv_hilo<<<(SEQL * DEPTH / 4) / 256, 256>>>(pos_emb + SEQL * DEPTH,
                                                    Bhi, Blo, SEQL * DEPTH / 4);
    ra_mma_gemm<<<dim3(SEQL / 128, QROWS / 128), 256, SMEM_DYN>>>(
        Ahi, Alo, Bhi, Blo, zb, QEp, DEPTH, 1.0f, 0, 1);

    // Attention (fp32 flash, causal, rel-bias gather)
    ra_attn_kernel<<<dim3(SEQL / 64, NHTOT), 256>>>(Qp, Kp, Vp, QEp, AOp);

    // Output projection
    ra_conv_hilo<<<n4x / 256, 256>>>(AOp, Ahi, Alo, n4x);
    ra_conv_wt<<<gwt, bwt>>>(Wo, Bhi, Blo);
    ra_mma_gemm<<<gproj, 256, SMEM_DYN>>>(Ahi, Alo, Bhi, Blo, bo, (float*)d_out,
                                          DMODEL, 1.0f, 0, 0);
}

// round 6
// speedup vs baseline: 1.7800x; 1.1015x over previous
#include <cuda_runtime.h>
#include <cuda_bf16.h>
#include <cstdint>

// Problem constants
#define SEQL   1024
#define DMODEL 1024
#define NBATCH 4
#define NHEADS 16
#define DEPTH  64
#define NHTOT  (NBATCH * NHEADS)   // 64
#define NLROWS (NBATCH * SEQL)     // 4096
#define QROWS  (NHTOT * SEQL)      // 65536

// ---------------------------------------------------------------------------
// Scratch (device globals; allocation-free per harness rules)
// ---------------------------------------------------------------------------
__device__ __align__(128) float g_QE[(size_t)QROWS * SEQL];   // diag-shifted band
__device__ float g_zbias[DMODEL];                             // zero-initialized
// bf16 hi/lo split buffers (raw u16 storage)
__device__ __align__(128) unsigned short g_Xhi[NLROWS * DMODEL]; // GEMM A / AO
__device__ __align__(128) unsigned short g_Xlo[NLROWS * DMODEL];
__device__ __align__(128) unsigned short g_Bhi[DMODEL * DMODEL]; // W^T or E
__device__ __align__(128) unsigned short g_Blo[DMODEL * DMODEL];
__device__ __align__(128) unsigned short g_Qhi[QROWS * DEPTH];
__device__ __align__(128) unsigned short g_Qlo[QROWS * DEPTH];
__device__ __align__(128) unsigned short g_Khi[QROWS * DEPTH];
__device__ __align__(128) unsigned short g_Klo[QROWS * DEPTH];
__device__ __align__(128) unsigned short g_Vhi[QROWS * DEPTH];
__device__ __align__(128) unsigned short g_Vlo[QROWS * DEPTH];
__device__ __align__(128) unsigned short g_Vthi[QROWS * DEPTH]; // [nh][64 d][1024 key]
__device__ __align__(128) unsigned short g_Vtlo[QROWS * DEPTH];

// ---------------------------------------------------------------------------
// Helpers
// ---------------------------------------------------------------------------
__device__ __forceinline__ uint32_t smem_u32(const void* p) {
    uint32_t a;
    asm("{ .reg .u64 t; cvta.to.shared.u64 t, %1; cvt.u32.u64 %0, t; }"
        : "=r"(a) : "l"(p));
    return a;
}
__device__ __forceinline__ uint32_t packbf(float a, float b) {
    __nv_bfloat162 t = __floats2bfloat162_rn(a, b);   // x=a (low), y=b
    return *reinterpret_cast<uint32_t*>(&t);
}
__device__ __forceinline__ void ldsm4(uint32_t addr, uint32_t& r0, uint32_t& r1,
                                      uint32_t& r2, uint32_t& r3) {
    asm volatile("ldmatrix.sync.aligned.m8n8.x4.shared.b16 {%0,%1,%2,%3}, [%4];"
                 : "=r"(r0), "=r"(r1), "=r"(r2), "=r"(r3) : "r"(addr));
}
#define MMA_BF16(c, a, b) \
    asm volatile("mma.sync.aligned.m16n8k16.row.col.f32.bf16.bf16.f32 " \
                 "{%0,%1,%2,%3}, {%4,%5,%6,%7}, {%8,%9}, {%0,%1,%2,%3};" \
                 : "+f"((c)[0]), "+f"((c)[1]), "+f"((c)[2]), "+f"((c)[3]) \
                 : "r"((a)[0]), "r"((a)[1]), "r"((a)[2]), "r"((a)[3]), \
                   "r"((b)[0]), "r"((b)[1]))

// ---------------------------------------------------------------------------
// Conversion kernels
// ---------------------------------------------------------------------------
__global__ __launch_bounds__(256) void ra_conv_hilo(
    const float* __restrict__ x, unsigned short* __restrict__ hi,
    unsigned short* __restrict__ lo, int n4)
{
    int i = blockIdx.x * 256 + threadIdx.x;
    if (i >= n4) return;
    float4 v = ((const float4*)x)[i];
    float f[4] = {v.x, v.y, v.z, v.w};
    unsigned short hs[4], ls[4];
    #pragma unroll
    for (int j = 0; j < 4; j++) {
        __nv_bfloat16 hb = __float2bfloat16(f[j]);
        __nv_bfloat16 lb = __float2bfloat16(f[j] - __bfloat162float(hb));
        hs[j] = __bfloat16_as_ushort(hb);
        ls[j] = __bfloat16_as_ushort(lb);
    }
    ((ushort4*)hi)[i] = make_ushort4(hs[0], hs[1], hs[2], hs[3]);
    ((ushort4*)lo)[i] = make_ushort4(ls[0], ls[1], ls[2], ls[3]);
}

// W [K=1024, N=1024] -> W^T hi/lo bf16 [N, K]
__global__ __launch_bounds__(256) void ra_conv_wt(
    const float* __restrict__ W, unsigned short* __restrict__ hiT,
    unsigned short* __restrict__ loT)
{
    __shared__ float tile[32][33];
    const int nx = blockIdx.x * 32 + threadIdx.x;
    const int k0 = blockIdx.y * 32;
    #pragma unroll
    for (int r = 0; r < 4; r++)
        tile[threadIdx.y + r * 8][threadIdx.x] =
            W[(size_t)(k0 + threadIdx.y + r * 8) * DMODEL + nx];
    __syncthreads();
    const int kx = k0 + threadIdx.x;
    const int n0 = blockIdx.x * 32;
    #pragma unroll
    for (int r = 0; r < 4; r++) {
        float v = tile[threadIdx.x][threadIdx.y + r * 8];
        __nv_bfloat16 hb = __float2bfloat16(v);
        __nv_bfloat16 lb = __float2bfloat16(v - __bfloat162float(hb));
        size_t o = (size_t)(n0 + threadIdx.y + r * 8) * DMODEL + kx;
        hiT[o] = __bfloat16_as_ushort(hb);
        loT[o] = __bfloat16_as_ushort(lb);
    }
}

// V [nh][1024 key][64 d] hi/lo -> Vt [nh][64 d][1024 key] hi/lo
__global__ __launch_bounds__(128) void ra_vt(
    const unsigned short* __restrict__ Vhi, const unsigned short* __restrict__ Vlo,
    unsigned short* __restrict__ Vthi, unsigned short* __restrict__ Vtlo)
{
    __shared__ unsigned short th[64 * 72];
    __shared__ unsigned short tl[64 * 72];
    const int head = blockIdx.y, kt = blockIdx.x;
    const int t = threadIdx.x, lr = t >> 1, lc = (t & 1) * 32;
    {
        const uint4* sh = (const uint4*)(Vhi + ((size_t)(head * SEQL + kt * 64 + lr)) * 64 + lc);
        const uint4* sl = (const uint4*)(Vlo + ((size_t)(head * SEQL + kt * 64 + lr)) * 64 + lc);
        uint4* dh = (uint4*)(th + lr * 72 + lc);
        uint4* dl = (uint4*)(tl + lr * 72 + lc);
        #pragma unroll
        for (int u = 0; u < 4; u++) { dh[u] = sh[u]; dl[u] = sl[u]; }
    }
    __syncthreads();
    // write: depth row lr, keys kt*64+lc..+31
    unsigned short* oh = Vthi + ((size_t)(head * 64 + lr)) * SEQL + kt * 64 + lc;
    unsigned short* ol = Vtlo + ((size_t)(head * 64 + lr)) * SEQL + kt * 64 + lc;
    #pragma unroll
    for (int v = 0; v < 4; v++) {
        uint32_t wh[4], wl[4];
        #pragma unroll
        for (int u = 0; u < 4; u++) {
            const int k = lc + v * 8 + u * 2;
            wh[u] = (uint32_t)th[k * 72 + lr] | ((uint32_t)th[(k + 1) * 72 + lr] << 16);
            wl[u] = (uint32_t)tl[k * 72 + lr] | ((uint32_t)tl[(k + 1) * 72 + lr] << 16);
        }
        ((uint4*)oh)[v] = make_uint4(wh[0], wh[1], wh[2], wh[3]);
        ((uint4*)ol)[v] = make_uint4(wl[0], wl[1], wl[2], wl[3]);
    }
}

// ---------------------------------------------------------------------------
// mma.sync split-bf16 GEMM with ldmatrix fragment loads.
// out = (Ahi+Alo)[M,KT] @ (Bhi+Blo)[N,KT]^T + bias, then scale.
// omode 0: f32 natural (outf). omode 1: u16 hi/lo head layout (outh/outl).
// omode 2: f32 diag-shifted QE band (outf), with band skip.
// ---------------------------------------------------------------------------
#define PITCH   40
#define A_HI_O  0
#define A_LO_O  (128 * PITCH)
#define B_HI_O  (2 * 128 * PITCH)
#define B_LO_O  (3 * 128 * PITCH)
#define STAGE_E (4 * 128 * PITCH)
#define SMEM_DYN (2 * STAGE_E * 2)

__global__ __launch_bounds__(256) void ra_mma_gemm(
    const unsigned short* __restrict__ Ahi, const unsigned short* __restrict__ Alo,
    const unsigned short* __restrict__ Bhi, const unsigned short* __restrict__ Blo,
    const float* __restrict__ bias, float* __restrict__ outf,
    unsigned short* __restrict__ outh, unsigned short* __restrict__ outl,
    int KT, float scale, int omode)
{
    const int m0 = blockIdx.y * 128;
    const int n0 = blockIdx.x * 128;
    if (omode == 2) {
        const int i0 = m0 & (SEQL - 1);
        if (n0 + 127 < (SEQL - 128) - i0) return;   // band never read
    }
    extern __shared__ unsigned short sm[];
    const uint32_t smb = smem_u32(sm);

    const int tid    = threadIdx.x;
    const int wid    = tid >> 5;
    const int lane   = tid & 31;
    const int warp_m = wid & 3;
    const int warp_n = wid >> 2;
    const int lrow16 = lane & 15;
    const int lcol8  = (lane >> 4) << 3;

    const int glr = tid >> 1;
    const int glc = (tid & 1) * 16;
    const size_t a_off = (size_t)(m0 + glr) * KT + glc;
    const size_t b_off = (size_t)(n0 + glr) * KT + glc;
    const int    s_off = glr * PITCH + glc;

    float acc[2][8][4];
    #pragma unroll
    for (int mt = 0; mt < 2; mt++)
        #pragma unroll
        for (int nt = 0; nt < 8; nt++)
            #pragma unroll
            for (int i = 0; i < 4; i++) acc[mt][nt][i] = 0.f;

    const int nch = KT >> 5;

    {
        #pragma unroll
        for (int u = 0; u < 2; u++) {
            *(uint4*)(sm + A_HI_O + s_off + u * 8) = *(const uint4*)(Ahi + a_off + u * 8);
            *(uint4*)(sm + A_LO_O + s_off + u * 8) = *(const uint4*)(Alo + a_off + u * 8);
            *(uint4*)(sm + B_HI_O + s_off + u * 8) = *(const uint4*)(Bhi + b_off + u * 8);
            *(uint4*)(sm + B_LO_O + s_off + u * 8) = *(const uint4*)(Blo + b_off + u * 8);
        }
    }
    __syncthreads();

    for (int c = 0; c < nch; c++) {
        uint4 pf[8];
        if (c + 1 < nch) {
            const size_t ka = a_off + (size_t)(c + 1) * 32;
            const size_t kb = b_off + (size_t)(c + 1) * 32;
            #pragma unroll
            for (int u = 0; u < 2; u++) {
                pf[u * 4 + 0] = *(const uint4*)(Ahi + ka + u * 8);
                pf[u * 4 + 1] = *(const uint4*)(Alo + ka + u * 8);
                pf[u * 4 + 2] = *(const uint4*)(Bhi + kb + u * 8);
                pf[u * 4 + 3] = *(const uint4*)(Blo + kb + u * 8);
            }
        }

        const uint32_t stb = smb + ((c & 1) * STAGE_E) * 2;
        #pragma unroll
        for (int kk = 0; kk < 32; kk += 16) {
            uint32_t ah[2][4], al[2][4];
            #pragma unroll
            for (int mt = 0; mt < 2; mt++) {
                const uint32_t aoff =
                    (uint32_t)((warp_m * 32 + mt * 16 + lrow16) * PITCH + kk + lcol8) * 2;
                ldsm4(stb + A_HI_O * 2 + aoff, ah[mt][0], ah[mt][1], ah[mt][2], ah[mt][3]);
                ldsm4(stb + A_LO_O * 2 + aoff, al[mt][0], al[mt][1], al[mt][2], al[mt][3]);
            }
            uint32_t bh[8][2], bl[8][2];
            #pragma unroll
            for (int grp = 0; grp < 4; grp++) {
                const uint32_t boff =
                    (uint32_t)((warp_n * 64 + grp * 16 + lrow16) * PITCH + kk + lcol8) * 2;
                uint32_t r0, r1, r2, r3;
                ldsm4(stb + B_HI_O * 2 + boff, r0, r1, r2, r3);
                bh[grp * 2][0] = r0; bh[grp * 2][1] = r2;
                bh[grp * 2 + 1][0] = r1; bh[grp * 2 + 1][1] = r3;
                ldsm4(stb + B_LO_O * 2 + boff, r0, r1, r2, r3);
                bl[grp * 2][0] = r0; bl[grp * 2][1] = r2;
                bl[grp * 2 + 1][0] = r1; bl[grp * 2 + 1][1] = r3;
            }
            #pragma unroll
            for (int mt = 0; mt < 2; mt++)
                #pragma unroll
                for (int nt = 0; nt < 8; nt++) {
                    MMA_BF16(acc[mt][nt], ah[mt], bh[nt]);
                    MMA_BF16(acc[mt][nt], ah[mt], bl[nt]);
                    MMA_BF16(acc[mt][nt], al[mt], bh[nt]);
                }
        }

        if (c + 1 < nch) {
            unsigned short* nst = sm + ((c + 1) & 1) * STAGE_E;
            #pragma unroll
            for (int u = 0; u < 2; u++) {
                *(uint4*)(nst + A_HI_O + s_off + u * 8) = pf[u * 4 + 0];
                *(uint4*)(nst + A_LO_O + s_off + u * 8) = pf[u * 4 + 1];
                *(uint4*)(nst + B_HI_O + s_off + u * 8) = pf[u * 4 + 2];
                *(uint4*)(nst + B_LO_O + s_off + u * 8) = pf[u * 4 + 3];
            }
            __syncthreads();
        }
    }

    // Epilogue
    const int rbase = m0 + warp_m * 32 + (lane >> 2);
    const int cbase = n0 + warp_n * 64 + (lane & 3) * 2;
    #pragma unroll
    for (int mt = 0; mt < 2; mt++) {
        #pragma unroll
        for (int nt = 0; nt < 8; nt++) {
            const int col = cbase + nt * 8;
            const float b0 = bias[col], b1 = bias[col + 1];
            #pragma unroll
            for (int half = 0; half < 2; half++) {
                const int row = rbase + mt * 16 + half * 8;
                const float v0 = (acc[mt][nt][half * 2 + 0] + b0) * scale;
                const float v1 = (acc[mt][nt][half * 2 + 1] + b1) * scale;
                if (omode == 0) {
                    *(float2*)(outf + (size_t)row * DMODEL + col) = make_float2(v0, v1);
                } else if (omode == 1) {
                    const int n = row >> 10, l = row & (SEQL - 1);
                    const int h = (col >> 6) & (NHEADS - 1);
                    const size_t oidx =
                        ((size_t)((n * NHEADS + h) * SEQL + l)) * DEPTH + (col & 63);
                    __nv_bfloat16 h0 = __float2bfloat16(v0);
                    __nv_bfloat16 h1 = __float2bfloat16(v1);
                    const float l0 = v0 - __bfloat162float(h0);
                    const float l1 = v1 - __bfloat162float(h1);
                    __nv_bfloat162 hp = __halves2bfloat162(h0, h1);
                    *(uint32_t*)(outh + oidx) = *reinterpret_cast<uint32_t*>(&hp);
                    *(uint32_t*)(outl + oidx) = packbf(l0, l1);
                } else {
                    const int i = row & (SEQL - 1);
                    const int j = col + i - (SEQL - 1);
                    if (j >= 0)     outf[(size_t)row * SEQL + j]     = v0;
                    if (j + 1 >= 0) outf[(size_t)row * SEQL + j + 1] = v1;
                }
            }
        }
    }
}

// ---------------------------------------------------------------------------
// MMA flash attention, 64-query tile, 4 warps, split-bf16 S and PV.
// Bias read from diag-shifted QE (aligned tile loads). Writes AO hi/lo bf16.
// ---------------------------------------------------------------------------
#define AT_KHI  0
#define AT_KLO  9216
#define AT_VHI  18432
#define AT_VLO  27648
#define AT_BIAS 36864
#define AT_SMEM (36864 + 64 * 68 * 4)   // 54272 bytes

__global__ __launch_bounds__(128) void ra_attn_mma(
    const unsigned short* __restrict__ Qhi, const unsigned short* __restrict__ Qlo,
    const unsigned short* __restrict__ Khi, const unsigned short* __restrict__ Klo,
    const unsigned short* __restrict__ Vthi, const unsigned short* __restrict__ Vtlo,
    const float* __restrict__ QE,
    unsigned short* __restrict__ AOhi, unsigned short* __restrict__ AOlo)
{
    extern __shared__ char smc[];
    const uint32_t smb = smem_u32(smc);
    const int nh = blockIdx.y;
    const int i0 = (int)(gridDim.x - 1 - blockIdx.x) * 64;   // big tiles first
    const int t = threadIdx.x;
    const int w = t >> 5, lane = t & 31;
    const int g = lane >> 2, q4 = lane & 3;
    const int lr = t >> 1, lc = (t & 1) * 32;
    const int lrow16 = lane & 15, lcol8 = (lane >> 4) << 3;

    // ---- Q fragments via staging in bias region ----
    uint32_t qh[4][4], ql[4][4];
    {
        const uint4* src = (const uint4*)(Qhi + ((size_t)(nh * SEQL + i0 + lr)) * 64 + lc);
        uint4* dst = (uint4*)(smc + AT_BIAS + (lr * 72 + lc) * 2);
        #pragma unroll
        for (int u = 0; u < 4; u++) dst[u] = src[u];
    }
    __syncthreads();
    #pragma unroll
    for (int kt = 0; kt < 4; kt++)
        ldsm4(smb + AT_BIAS + (uint32_t)((16 * w + lrow16) * 72 + kt * 16 + lcol8) * 2,
              qh[kt][0], qh[kt][1], qh[kt][2], qh[kt][3]);
    __syncthreads();
    {
        const uint4* src = (const uint4*)(Qlo + ((size_t)(nh * SEQL + i0 + lr)) * 64 + lc);
        uint4* dst = (uint4*)(smc + AT_BIAS + (lr * 72 + lc) * 2);
        #pragma unroll
        for (int u = 0; u < 4; u++) dst[u] = src[u];
    }
    __syncthreads();
    #pragma unroll
    for (int kt = 0; kt < 4; kt++)
        ldsm4(smb + AT_BIAS + (uint32_t)((16 * w + lrow16) * 72 + kt * 16 + lcol8) * 2,
              ql[kt][0], ql[kt][1], ql[kt][2], ql[kt][3]);

    float o[8][4];
    #pragma unroll
    for (int nt = 0; nt < 8; nt++)
        #pragma unroll
        for (int i = 0; i < 4; i++) o[nt][i] = 0.f;
    float rm[2] = {-1e30f, -1e30f};
    float rl[2] = {0.f, 0.f};

    for (int j0 = 0; j0 <= i0; j0 += 64) {
        __syncthreads();   // smem free (prev iter consumed; Q frags latched)
        // producer: K hi/lo, Vt hi/lo, bias tile
        {
            const uint4* skh = (const uint4*)(Khi + ((size_t)(nh * SEQL + j0 + lr)) * 64 + lc);
            const uint4* skl = (const uint4*)(Klo + ((size_t)(nh * SEQL + j0 + lr)) * 64 + lc);
            uint4* dkh = (uint4*)(smc + AT_KHI + (lr * 72 + lc) * 2);
            uint4* dkl = (uint4*)(smc + AT_KLO + (lr * 72 + lc) * 2);
            const uint4* svh = (const uint4*)(Vthi + ((size_t)(nh * 64 + lr)) * SEQL + j0 + lc);
            const uint4* svl = (const uint4*)(Vtlo + ((size_t)(nh * 64 + lr)) * SEQL + j0 + lc);
            uint4* dvh = (uint4*)(smc + AT_VHI + (lr * 72 + lc) * 2);
            uint4* dvl = (uint4*)(smc + AT_VLO + (lr * 72 + lc) * 2);
            #pragma unroll
            for (int u = 0; u < 4; u++) {
                dkh[u] = skh[u]; dkl[u] = skl[u];
                dvh[u] = svh[u]; dvl[u] = svl[u];
            }
            const float4* sbq = (const float4*)(QE + (size_t)(nh * SEQL + i0 + lr) * SEQL + j0 + lc);
            float4* dbq = (float4*)(smc + AT_BIAS + (lr * 68 + lc) * 4);
            #pragma unroll
            for (int u = 0; u < 8; u++) dbq[u] = sbq[u];
        }
        __syncthreads();

        // ---- S = QK^T (3-term split) ----
        float s[8][4];
        #pragma unroll
        for (int nt = 0; nt < 8; nt++)
            #pragma unroll
            for (int i = 0; i < 4; i++) s[nt][i] = 0.f;
        #pragma unroll
        for (int kt = 0; kt < 4; kt++) {
            uint32_t kbh[8][2], kbl[8][2];
            #pragma unroll
            for (int grp = 0; grp < 4; grp++) {
                const uint32_t off = (uint32_t)((grp * 16 + lrow16) * 72 + kt * 16 + lcol8) * 2;
                uint32_t r0, r1, r2, r3;
                ldsm4(smb + AT_KHI + off, r0, r1, r2, r3);
                kbh[grp * 2][0] = r0; kbh[grp * 2][1] = r2;
                kbh[grp * 2 + 1][0] = r1; kbh[grp * 2 + 1][1] = r3;
                ldsm4(smb + AT_KLO + off, r0, r1, r2, r3);
                kbl[grp * 2][0] = r0; kbl[grp * 2][1] = r2;
                kbl[grp * 2 + 1][0] = r1; kbl[grp * 2 + 1][1] = r3;
            }
            #pragma unroll
            for (int nt = 0; nt < 8; nt++) {
                MMA_BF16(s[nt], qh[kt], kbh[nt]);
                MMA_BF16(s[nt], qh[kt], kbl[nt]);
                MMA_BF16(s[nt], ql[kt], kbh[nt]);
            }
        }

        // ---- bias + causal mask ----
        const int r0l = 16 * w + g, r1l = r0l + 8;
        #pragma unroll
        for (int nt = 0; nt < 8; nt++) {
            const int cl = nt * 8 + q4 * 2;
            const float2 b0 = *(const float2*)(smc + AT_BIAS + (r0l * 68 + cl) * 4);
            const float2 b1 = *(const float2*)(smc + AT_BIAS + (r1l * 68 + cl) * 4);
            s[nt][0] += b0.x; s[nt][1] += b0.y;
            s[nt][2] += b1.x; s[nt][3] += b1.y;
        }
        if (j0 == i0) {
            #pragma unroll
            for (int nt = 0; nt < 8; nt++) {
                const int cl = nt * 8 + q4 * 2;
                if (cl     > r0l) s[nt][0] = -1e30f;
                if (cl + 1 > r0l) s[nt][1] = -1e30f;
                if (cl     > r1l) s[nt][2] = -1e30f;
                if (cl + 1 > r1l) s[nt][3] = -1e30f;
            }
        }

        // ---- online softmax ----
        float mx0 = -1e30f, mx1 = -1e30f;
        #pragma unroll
        for (int nt = 0; nt < 8; nt++) {
            mx0 = fmaxf(mx0, fmaxf(s[nt][0], s[nt][1]));
            mx1 = fmaxf(mx1, fmaxf(s[nt][2], s[nt][3]));
        }
        mx0 = fmaxf(mx0, __shfl_xor_sync(0xffffffffu, mx0, 1));
        mx0 = fmaxf(mx0, __shfl_xor_sync(0xffffffffu, mx0, 2));
        mx1 = fmaxf(mx1, __shfl_xor_sync(0xffffffffu, mx1, 1));
        mx1 = fmaxf(mx1, __shfl_xor_sync(0xffffffffu, mx1, 2));
        const float m0n = fmaxf(rm[0], mx0);
        const float m1n = fmaxf(rm[1], mx1);
        const float a0 = __expf(rm[0] - m0n);
        const float a1 = __expf(rm[1] - m1n);
        float ps0 = 0.f, ps1 = 0.f;
        uint32_t ph[4][4], pl[4][4];
        #pragma unroll
        for (int nt = 0; nt < 8; nt++) {
            const float p0 = __expf(s[nt][0] - m0n);
            const float p1 = __expf(s[nt][1] - m0n);
            const float p2 = __expf(s[nt][2] - m1n);
            const float p3 = __expf(s[nt][3] - m1n);
            ps0 += p0 + p1; ps1 += p2 + p3;
            const __nv_bfloat16 h0 = __float2bfloat16(p0);
            const __nv_bfloat16 h1 = __float2bfloat16(p1);
            const __nv_bfloat16 h2 = __float2bfloat16(p2);
            const __nv_bfloat16 h3 = __float2bfloat16(p3);
            const float l0 = p0 - __bfloat162float(h0);
            const float l1 = p1 - __bfloat162float(h1);
            const float l2 = p2 - __bfloat162float(h2);
            const float l3 = p3 - __bfloat162float(h3);
            const int kt = nt >> 1, sl = (nt & 1) * 2;
            __nv_bfloat162 hp01 = __halves2bfloat162(h0, h1);
            __nv_bfloat162 hp23 = __halves2bfloat162(h2, h3);
            ph[kt][sl + 0] = *reinterpret_cast<uint32_t*>(&hp01);
            ph[kt][sl + 1] = *reinterpret_cast<uint32_t*>(&hp23);
            pl[kt][sl + 0] = packbf(l0, l1);
            pl[kt][sl + 1] = packbf(l2, l3);
        }
        ps0 += __shfl_xor_sync(0xffffffffu, ps0, 1);
        ps0 += __shfl_xor_sync(0xffffffffu, ps0, 2);
        ps1 += __shfl_xor_sync(0xffffffffu, ps1, 1);
        ps1 += __shfl_xor_sync(0xffffffffu, ps1, 2);
        rl[0] = rl[0] * a0 + ps0;
        rl[1] = rl[1] * a1 + ps1;
        rm[0] = m0n; rm[1] = m1n;
        #pragma unroll
        for (int nt = 0; nt < 8; nt++) {
            o[nt][0] *= a0; o[nt][1] *= a0;
            o[nt][2] *= a1; o[nt][3] *= a1;
        }

        // ---- O += P @ V (3-term split) ----
        #pragma unroll
        for (int kt = 0; kt < 4; kt++) {
            uint32_t vbh[8][2], vbl[8][2];
            #pragma unroll
            for (int grp = 0; grp < 4; grp++) {
                const uint32_t off = (uint32_t)((grp * 16 + lrow16) * 72 + kt * 16 + lcol8) * 2;
                uint32_t r0, r1, r2, r3;
                ldsm4(smb + AT_VHI + off, r0, r1, r2, r3);
                vbh[grp * 2][0] = r0; vbh[grp * 2][1] = r2;
                vbh[grp * 2 + 1][0] = r1; vbh[grp * 2 + 1][1] = r3;
                ldsm4(smb + AT_VLO + off, r0, r1, r2, r3);
                vbl[grp * 2][0] = r0; vbl[grp * 2][1] = r2;
                vbl[grp * 2 + 1][0] = r1; vbl[grp * 2 + 1][1] = r3;
            }
            #pragma unroll
            for (int nt = 0; nt < 8; nt++) {
                MMA_BF16(o[nt], ph[kt], vbh[nt]);
                MMA_BF16(o[nt], ph[kt], vbl[nt]);
                MMA_BF16(o[nt], pl[kt], vbh[nt]);
            }
        }
    }

    // ---- epilogue: normalize, split, write AO hi/lo (natural layout) ----
    const float inv0 = 1.f / rl[0], inv1 = 1.f / rl[1];
    const int n = nh >> 4, h = nh & (NHEADS - 1);
    const int r0g = i0 + 16 * w + g, r1g = r0g + 8;
    #pragma unroll
    for (int nt = 0; nt < 8; nt++) {
        const int col = h * 64 + nt * 8 + q4 * 2;
        const float v0 = o[nt][0] * inv0, v1 = o[nt][1] * inv0;
        const float v2 = o[nt][2] * inv1, v3 = o[nt][3] * inv1;
        const __nv_bfloat16 h0 = __float2bfloat16(v0), h1 = __float2bfloat16(v1);
        const __nv_bfloat16 h2 = __float2bfloat16(v2), h3 = __float2bfloat16(v3);
        const size_t idx0 = ((size_t)(n * SEQL + r0g)) * DMODEL + col;
        const size_t idx1 = ((size_t)(n * SEQL + r1g)) * DMODEL + col;
        __nv_bfloat162 hp01 = __halves2bfloat162(h0, h1);
        __nv_bfloat162 hp23 = __halves2bfloat162(h2, h3);
        *(uint32_t*)(AOhi + idx0) = *reinterpret_cast<uint32_t*>(&hp01);
        *(uint32_t*)(AOhi + idx1) = *reinterpret_cast<uint32_t*>(&hp23);
        *(uint32_t*)(AOlo + idx0) = packbf(v0 - __bfloat162float(h0),
                                           v1 - __bfloat162float(h1));
        *(uint32_t*)(AOlo + idx1) = packbf(v2 - __bfloat162float(h2),
                                           v3 - __bfloat162float(h3));
    }
}

// ---------------------------------------------------------------------------
extern "C" void kernel_launch(void* const* d_in, const int* in_sizes, int n_in,
                              void* d_out, int out_size)
{
    (void)in_sizes; (void)n_in; (void)out_size;
    const float* q_in    = (const float*)d_in[0];
    const float* k_in    = (const float*)d_in[1];
    const float* v_in    = (const float*)d_in[2];
    /* d_in[3] = mask (triu k=1) — handled analytically */
    const float* Wq      = (const float*)d_in[4];
    const float* bq      = (const float*)d_in[5];
    const float* Wk      = (const float*)d_in[6];
    const float* bk      = (const float*)d_in[7];
    const float* Wv      = (const float*)d_in[8];
    const float* bv      = (const float*)d_in[9];
    const float* Wo      = (const float*)d_in[10];
    const float* bo      = (const float*)d_in[11];
    const float* pos_emb = (const float*)d_in[12];

    float *QEp, *zb;
    unsigned short *Xhi, *Xlo, *Bh, *Bl, *Qh, *Ql, *Kh, *Kl, *Vh, *Vl, *Vth, *Vtl;
    cudaGetSymbolAddress((void**)&QEp, g_QE);
    cudaGetSymbolAddress((void**)&zb,  g_zbias);
    cudaGetSymbolAddress((void**)&Xhi, g_Xhi);
    cudaGetSymbolAddress((void**)&Xlo, g_Xlo);
    cudaGetSymbolAddress((void**)&Bh,  g_Bhi);
    cudaGetSymbolAddress((void**)&Bl,  g_Blo);
    cudaGetSymbolAddress((void**)&Qh,  g_Qhi);
    cudaGetSymbolAddress((void**)&Ql,  g_Qlo);
    cudaGetSymbolAddress((void**)&Kh,  g_Khi);
    cudaGetSymbolAddress((void**)&Kl,  g_Klo);
    cudaGetSymbolAddress((void**)&Vh,  g_Vhi);
    cudaGetSymbolAddress((void**)&Vl,  g_Vlo);
    cudaGetSymbolAddress((void**)&Vth, g_Vthi);
    cudaGetSymbolAddress((void**)&Vtl, g_Vtlo);

    cudaFuncSetAttribute(ra_mma_gemm, cudaFuncAttributeMaxDynamicSharedMemorySize,
                         SMEM_DYN);
    cudaFuncSetAttribute(ra_attn_mma, cudaFuncAttributeMaxDynamicSharedMemorySize,
                         AT_SMEM);

    const dim3 gwt(32, 32);
    const dim3 bwt(32, 8);
    const dim3 gproj(DMODEL / 128, NLROWS / 128);  // (8, 32)
    const int  n4x = (NLROWS * DMODEL) / 4;

    // Q projection (scale folds in 1/sqrt(d)); writes bf16 hi/lo head layout
    ra_conv_hilo<<<n4x / 256, 256>>>(q_in, Xhi, Xlo, n4x);
    ra_conv_wt<<<gwt, bwt>>>(Wq, Bh, Bl);
    ra_mma_gemm<<<gproj, 256, SMEM_DYN>>>(Xhi, Xlo, Bh, Bl, bq,
                                          nullptr, Qh, Ql, DMODEL, 0.125f, 1);
    // K projection
    ra_conv_hilo<<<n4x / 256, 256>>>(k_in, Xhi, Xlo, n4x);
    ra_conv_wt<<<gwt, bwt>>>(Wk, Bh, Bl);
    ra_mma_gemm<<<gproj, 256, SMEM_DYN>>>(Xhi, Xlo, Bh, Bl, bk,
                                          nullptr, Kh, Kl, DMODEL, 1.0f, 1);
    // V projection + per-head transpose
    ra_conv_hilo<<<n4x / 256, 256>>>(v_in, Xhi, Xlo, n4x);
    ra_conv_wt<<<gwt, bwt>>>(Wv, Bh, Bl);
    ra_mma_gemm<<<gproj, 256, SMEM_DYN>>>(Xhi, Xlo, Bh, Bl, bv,
                                          nullptr, Vh, Vl, DMODEL, 1.0f, 1);
    ra_vt<<<dim3(16, NHTOT), 128>>>(Vh, Vl, Vth, Vtl);

    // QE = Q @ E^T (K=64), stored diag-shifted, band-skipped
    ra_conv_hilo<<<(SEQL * DEPTH / 4) / 256, 256>>>(pos_emb + SEQL * DEPTH,
                                                    Bh, Bl, SEQL * DEPTH / 4);
    ra_mma_gemm<<<dim3(SEQL / 128, QROWS / 128), 256, SMEM_DYN>>>(
        Qh, Ql, Bh, Bl, zb, QEp, nullptr, nullptr, DEPTH, 1.0f, 2);

    // MMA flash attention -> AO hi/lo (reuses X buffers)
    ra_attn_mma<<<dim3(SEQL / 64, NHTOT), 128, AT_SMEM>>>(
        Qh, Ql, Kh, Kl, Vth, Vtl, QEp, Xhi, Xlo);

    // Output projection -> f32 d_out
    ra_conv_wt<<<gwt, bwt>>>(Wo, Bh, Bl);
    ra_mma_gemm<<<gproj, 256, SMEM_DYN>>>(Xhi, Xlo, Bh, Bl, bo,
                                          (float*)d_out, nullptr, nullptr,
                                          DMODEL, 1.0f, 0);
}

// round 8
// speedup vs baseline: 2.0255x; 1.1379x over previous
#include <cuda_runtime.h>
#include <cuda_bf16.h>
#include <cstdint>

// Problem constants
#define SEQL   1024
#define DMODEL 1024
#define NBATCH 4
#define NHEADS 16
#define DEPTH  64
#define NHTOT  (NBATCH * NHEADS)   // 64
#define NLROWS (NBATCH * SEQL)     // 4096
#define QROWS  (NHTOT * SEQL)      // 65536

// ---------------------------------------------------------------------------
// Scratch (device globals; allocation-free per harness rules)
// ---------------------------------------------------------------------------
__device__ __align__(128) float g_QE[(size_t)QROWS * SEQL];   // diag-shifted band
__device__ float g_zbias[DMODEL];                             // zero-initialized
// bf16 hi/lo split buffers
__device__ __align__(128) unsigned short g_Xhi[3][NLROWS * DMODEL]; // q/k/v ins; [0] reused for AO
__device__ __align__(128) unsigned short g_Xlo[3][NLROWS * DMODEL];
__device__ __align__(128) unsigned short g_Bhi[4][DMODEL * DMODEL]; // Wq/Wk/Wv/Wo ^T
__device__ __align__(128) unsigned short g_Blo[4][DMODEL * DMODEL];
__device__ __align__(128) unsigned short g_Ehi[SEQL * DEPTH];
__device__ __align__(128) unsigned short g_Elo[SEQL * DEPTH];
__device__ __align__(128) unsigned short g_Qhi[QROWS * DEPTH];
__device__ __align__(128) unsigned short g_Qlo[QROWS * DEPTH];
__device__ __align__(128) unsigned short g_Khi[QROWS * DEPTH];
__device__ __align__(128) unsigned short g_Klo[QROWS * DEPTH];
__device__ __align__(128) unsigned short g_Vhi[QROWS * DEPTH];
__device__ __align__(128) unsigned short g_Vlo[QROWS * DEPTH];
__device__ __align__(128) unsigned short g_Vthi[QROWS * DEPTH]; // [nh][64 d][1024 key]
__device__ __align__(128) unsigned short g_Vtlo[QROWS * DEPTH];

// ---------------------------------------------------------------------------
// Helpers
// ---------------------------------------------------------------------------
__device__ __forceinline__ uint32_t smem_u32(const void* p) {
    uint32_t a;
    asm("{ .reg .u64 t; cvta.to.shared.u64 t, %1; cvt.u32.u64 %0, t; }"
        : "=r"(a) : "l"(p));
    return a;
}
__device__ __forceinline__ uint32_t packbf(float a, float b) {
    __nv_bfloat162 t = __floats2bfloat162_rn(a, b);   // x=a (low), y=b (high)
    return *reinterpret_cast<uint32_t*>(&t);
}
__device__ __forceinline__ void ldsm4(uint32_t addr, uint32_t& r0, uint32_t& r1,
                                      uint32_t& r2, uint32_t& r3) {
    asm volatile("ldmatrix.sync.aligned.m8n8.x4.shared.b16 {%0,%1,%2,%3}, [%4];"
                 : "=r"(r0), "=r"(r1), "=r"(r2), "=r"(r3) : "r"(addr));
}
__device__ __forceinline__ void cp16(uint32_t saddr, const void* g) {
    asm volatile("cp.async.cg.shared.global [%0], [%1], 16;"
                 :: "r"(saddr), "l"(g) : "memory");
}
__device__ __forceinline__ void cp_commit() {
    asm volatile("cp.async.commit_group;" ::: "memory");
}
template <int N>
__device__ __forceinline__ void cp_wait() {
    asm volatile("cp.async.wait_group %0;" :: "n"(N) : "memory");
}
#define MMA_BF16(c, a, b) \
    asm volatile("mma.sync.aligned.m16n8k16.row.col.f32.bf16.bf16.f32 " \
                 "{%0,%1,%2,%3}, {%4,%5,%6,%7}, {%8,%9}, {%0,%1,%2,%3};" \
                 : "+f"((c)[0]), "+f"((c)[1]), "+f"((c)[2]), "+f"((c)[3]) \
                 : "r"((a)[0]), "r"((a)[1]), "r"((a)[2]), "r"((a)[3]), \
                   "r"((b)[0]), "r"((b)[1]))

// ---------------------------------------------------------------------------
// Conversion kernels (fused multi-tensor variants)
// ---------------------------------------------------------------------------
__global__ __launch_bounds__(256) void ra_conv_hilo3(
    const float* __restrict__ x0, const float* __restrict__ x1,
    const float* __restrict__ x2,
    unsigned short* __restrict__ h0, unsigned short* __restrict__ l0,
    unsigned short* __restrict__ h1, unsigned short* __restrict__ l1,
    unsigned short* __restrict__ h2, unsigned short* __restrict__ l2, int n4)
{
    const int z = blockIdx.y;
    const float* x = z == 0 ? x0 : (z == 1 ? x1 : x2);
    unsigned short* hi = z == 0 ? h0 : (z == 1 ? h1 : h2);
    unsigned short* lo = z == 0 ? l0 : (z == 1 ? l1 : l2);
    int i = blockIdx.x * 256 + threadIdx.x;
    if (i >= n4) return;
    float4 v = ((const float4*)x)[i];
    uint32_t hp0 = packbf(v.x, v.y);
    uint32_t hp1 = packbf(v.z, v.w);
    uint32_t lp0 = packbf(v.x - __uint_as_float(hp0 << 16),
                          v.y - __uint_as_float(hp0 & 0xffff0000u));
    uint32_t lp1 = packbf(v.z - __uint_as_float(hp1 << 16),
                          v.w - __uint_as_float(hp1 & 0xffff0000u));
    ((uint2*)hi)[i] = make_uint2(hp0, hp1);
    ((uint2*)lo)[i] = make_uint2(lp0, lp1);
}

__global__ __launch_bounds__(256) void ra_conv_hilo(
    const float* __restrict__ x, unsigned short* __restrict__ hi,
    unsigned short* __restrict__ lo, int n4)
{
    int i = blockIdx.x * 256 + threadIdx.x;
    if (i >= n4) return;
    float4 v = ((const float4*)x)[i];
    uint32_t hp0 = packbf(v.x, v.y);
    uint32_t hp1 = packbf(v.z, v.w);
    uint32_t lp0 = packbf(v.x - __uint_as_float(hp0 << 16),
                          v.y - __uint_as_float(hp0 & 0xffff0000u));
    uint32_t lp1 = packbf(v.z - __uint_as_float(hp1 << 16),
                          v.w - __uint_as_float(hp1 & 0xffff0000u));
    ((uint2*)hi)[i] = make_uint2(hp0, hp1);
    ((uint2*)lo)[i] = make_uint2(lp0, lp1);
}

// W [K=1024, N=1024] -> W^T hi/lo bf16 [N, K]; 4 weights fused via blockIdx.z
__global__ __launch_bounds__(256) void ra_conv_wt4(
    const float* __restrict__ W0, const float* __restrict__ W1,
    const float* __restrict__ W2, const float* __restrict__ W3,
    unsigned short* __restrict__ h0, unsigned short* __restrict__ l0,
    unsigned short* __restrict__ h1, unsigned short* __restrict__ l1,
    unsigned short* __restrict__ h2, unsigned short* __restrict__ l2,
    unsigned short* __restrict__ h3, unsigned short* __restrict__ l3)
{
    const int z = blockIdx.z;
    const float* W = z == 0 ? W0 : (z == 1 ? W1 : (z == 2 ? W2 : W3));
    unsigned short* hiT = z == 0 ? h0 : (z == 1 ? h1 : (z == 2 ? h2 : h3));
    unsigned short* loT = z == 0 ? l0 : (z == 1 ? l1 : (z == 2 ? l2 : l3));
    __shared__ float tile[32][33];
    const int nx = blockIdx.x * 32 + threadIdx.x;
    const int k0 = blockIdx.y * 32;
    #pragma unroll
    for (int r = 0; r < 4; r++)
        tile[threadIdx.y + r * 8][threadIdx.x] =
            W[(size_t)(k0 + threadIdx.y + r * 8) * DMODEL + nx];
    __syncthreads();
    const int kx = k0 + threadIdx.x;
    const int n0 = blockIdx.x * 32;
    #pragma unroll
    for (int r = 0; r < 4; r++) {
        float v = tile[threadIdx.x][threadIdx.y + r * 8];
        __nv_bfloat16 hb = __float2bfloat16(v);
        __nv_bfloat16 lb = __float2bfloat16(v - __bfloat162float(hb));
        size_t o = (size_t)(n0 + threadIdx.y + r * 8) * DMODEL + kx;
        hiT[o] = __bfloat16_as_ushort(hb);
        loT[o] = __bfloat16_as_ushort(lb);
    }
}

// V [nh][1024 key][64 d] hi/lo -> Vt [nh][64 d][1024 key] hi/lo
__global__ __launch_bounds__(128) void ra_vt(
    const unsigned short* __restrict__ Vhi, const unsigned short* __restrict__ Vlo,
    unsigned short* __restrict__ Vthi, unsigned short* __restrict__ Vtlo)
{
    __shared__ unsigned short th[64 * 72];
    __shared__ unsigned short tl[64 * 72];
    const int head = blockIdx.y, kt = blockIdx.x;
    const int t = threadIdx.x, lr = t >> 1, lc = (t & 1) * 32;
    {
        const uint4* sh = (const uint4*)(Vhi + ((size_t)(head * SEQL + kt * 64 + lr)) * 64 + lc);
        const uint4* sl = (const uint4*)(Vlo + ((size_t)(head * SEQL + kt * 64 + lr)) * 64 + lc);
        uint4* dh = (uint4*)(th + lr * 72 + lc);
        uint4* dl = (uint4*)(tl + lr * 72 + lc);
        #pragma unroll
        for (int u = 0; u < 4; u++) { dh[u] = sh[u]; dl[u] = sl[u]; }
    }
    __syncthreads();
    unsigned short* oh = Vthi + ((size_t)(head * 64 + lr)) * SEQL + kt * 64 + lc;
    unsigned short* ol = Vtlo + ((size_t)(head * 64 + lr)) * SEQL + kt * 64 + lc;
    #pragma unroll
    for (int v = 0; v < 4; v++) {
        uint32_t wh[4], wl[4];
        #pragma unroll
        for (int u = 0; u < 4; u++) {
            const int k = lc + v * 8 + u * 2;
            wh[u] = (uint32_t)th[k * 72 + lr] | ((uint32_t)th[(k + 1) * 72 + lr] << 16);
            wl[u] = (uint32_t)tl[k * 72 + lr] | ((uint32_t)tl[(k + 1) * 72 + lr] << 16);
        }
        ((uint4*)oh)[v] = make_uint4(wh[0], wh[1], wh[2], wh[3]);
        ((uint4*)ol)[v] = make_uint4(wl[0], wl[1], wl[2], wl[3]);
    }
}

// ---------------------------------------------------------------------------
// mma.sync split-bf16 GEMM, cp.async 2-stage pipeline, ldmatrix frags.
// omode 0: f32 natural. omode 1: bf16 hi/lo head layout. omode 2: QE band.
// ---------------------------------------------------------------------------
#define PITCH   40
#define A_HI_O  0
#define A_LO_O  (128 * PITCH)
#define B_HI_O  (2 * 128 * PITCH)
#define B_LO_O  (3 * 128 * PITCH)
#define STAGE_E (4 * 128 * PITCH)
#define SMEM_DYN (2 * STAGE_E * 2)

#define GISSUE(c) do { \
    const uint32_t sb_ = smb + (uint32_t)(((c) & 1) * (STAGE_E * 2)); \
    const size_t ka_ = a_off + (size_t)(c) * 32; \
    const size_t kb_ = b_off + (size_t)(c) * 32; \
    cp16(sb_ + (A_HI_O + s_off) * 2,      Ahi + ka_); \
    cp16(sb_ + (A_HI_O + s_off) * 2 + 16, Ahi + ka_ + 8); \
    cp16(sb_ + (A_LO_O + s_off) * 2,      Alo + ka_); \
    cp16(sb_ + (A_LO_O + s_off) * 2 + 16, Alo + ka_ + 8); \
    cp16(sb_ + (B_HI_O + s_off) * 2,      Bhi + kb_); \
    cp16(sb_ + (B_HI_O + s_off) * 2 + 16, Bhi + kb_ + 8); \
    cp16(sb_ + (B_LO_O + s_off) * 2,      Blo + kb_); \
    cp16(sb_ + (B_LO_O + s_off) * 2 + 16, Blo + kb_ + 8); \
} while (0)

__global__ __launch_bounds__(256) void ra_mma_gemm(
    const unsigned short* __restrict__ Ahi, const unsigned short* __restrict__ Alo,
    const unsigned short* __restrict__ Bhi, const unsigned short* __restrict__ Blo,
    const float* __restrict__ bias, float* __restrict__ outf,
    unsigned short* __restrict__ outh, unsigned short* __restrict__ outl,
    int KT, float scale, int omode)
{
    const int m0 = blockIdx.y * 128;
    const int n0 = blockIdx.x * 128;
    if (omode == 2) {
        const int i0 = m0 & (SEQL - 1);
        if (n0 + 127 < (SEQL - 128) - i0) return;   // band never read
    }
    extern __shared__ unsigned short sm[];
    const uint32_t smb = smem_u32(sm);

    const int tid    = threadIdx.x;
    const int wid    = tid >> 5;
    const int lane   = tid & 31;
    const int warp_m = wid & 3;
    const int warp_n = wid >> 2;
    const int lrow16 = lane & 15;
    const int lcol8  = (lane >> 4) << 3;

    const int glr = tid >> 1;
    const int glc = (tid & 1) * 16;
    const size_t a_off = (size_t)(m0 + glr) * KT + glc;
    const size_t b_off = (size_t)(n0 + glr) * KT + glc;
    const int    s_off = glr * PITCH + glc;

    float acc[2][8][4];
    #pragma unroll
    for (int mt = 0; mt < 2; mt++)
        #pragma unroll
        for (int nt = 0; nt < 8; nt++)
            #pragma unroll
            for (int i = 0; i < 4; i++) acc[mt][nt][i] = 0.f;

    const int nch = KT >> 5;

    GISSUE(0);
    cp_commit();

    for (int c = 0; c < nch; c++) {
        if (c + 1 < nch) {
            GISSUE(c + 1);
            cp_commit();
            cp_wait<1>();
        } else {
            cp_wait<0>();
        }
        __syncthreads();

        const uint32_t stb = smb + (uint32_t)((c & 1) * (STAGE_E * 2));
        #pragma unroll
        for (int kk = 0; kk < 32; kk += 16) {
            uint32_t ah[2][4], al[2][4];
            #pragma unroll
            for (int mt = 0; mt < 2; mt++) {
                const uint32_t aoff =
                    (uint32_t)((warp_m * 32 + mt * 16 + lrow16) * PITCH + kk + lcol8) * 2;
                ldsm4(stb + A_HI_O * 2 + aoff, ah[mt][0], ah[mt][1], ah[mt][2], ah[mt][3]);
                ldsm4(stb + A_LO_O * 2 + aoff, al[mt][0], al[mt][1], al[mt][2], al[mt][3]);
            }
            uint32_t bh[8][2], bl[8][2];
            #pragma unroll
            for (int grp = 0; grp < 4; grp++) {
                const uint32_t boff =
                    (uint32_t)((warp_n * 64 + grp * 16 + lrow16) * PITCH + kk + lcol8) * 2;
                uint32_t r0, r1, r2, r3;
                ldsm4(stb + B_HI_O * 2 + boff, r0, r1, r2, r3);
                bh[grp * 2][0] = r0; bh[grp * 2][1] = r2;
                bh[grp * 2 + 1][0] = r1; bh[grp * 2 + 1][1] = r3;
                ldsm4(stb + B_LO_O * 2 + boff, r0, r1, r2, r3);
                bl[grp * 2][0] = r0; bl[grp * 2][1] = r2;
                bl[grp * 2 + 1][0] = r1; bl[grp * 2 + 1][1] = r3;
            }
            #pragma unroll
            for (int mt = 0; mt < 2; mt++)
                #pragma unroll
                for (int nt = 0; nt < 8; nt++) {
                    MMA_BF16(acc[mt][nt], ah[mt], bh[nt]);
                    MMA_BF16(acc[mt][nt], ah[mt], bl[nt]);
                    MMA_BF16(acc[mt][nt], al[mt], bh[nt]);
                }
        }
        __syncthreads();
    }

    // Epilogue
    const int rbase = m0 + warp_m * 32 + (lane >> 2);
    const int cbase = n0 + warp_n * 64 + (lane & 3) * 2;
    #pragma unroll
    for (int mt = 0; mt < 2; mt++) {
        #pragma unroll
        for (int nt = 0; nt < 8; nt++) {
            const int col = cbase + nt * 8;
            const float b0 = bias[col], b1 = bias[col + 1];
            #pragma unroll
            for (int half = 0; half < 2; half++) {
                const int row = rbase + mt * 16 + half * 8;
                const float v0 = (acc[mt][nt][half * 2 + 0] + b0) * scale;
                const float v1 = (acc[mt][nt][half * 2 + 1] + b1) * scale;
                if (omode == 0) {
                    *(float2*)(outf + (size_t)row * DMODEL + col) = make_float2(v0, v1);
                } else if (omode == 1) {
                    const int n = row >> 10, l = row & (SEQL - 1);
                    const int h = (col >> 6) & (NHEADS - 1);
                    const size_t oidx =
                        ((size_t)((n * NHEADS + h) * SEQL + l)) * DEPTH + (col & 63);
                    const uint32_t hp = packbf(v0, v1);
                    *(uint32_t*)(outh + oidx) = hp;
                    *(uint32_t*)(outl + oidx) =
                        packbf(v0 - __uint_as_float(hp << 16),
                               v1 - __uint_as_float(hp & 0xffff0000u));
                } else {
                    const int i = row & (SEQL - 1);
                    const int j = col + i - (SEQL - 1);
                    if (j >= 0)     outf[(size_t)row * SEQL + j]     = v0;
                    if (j + 1 >= 0) outf[(size_t)row * SEQL + j + 1] = v1;
                }
            }
        }
    }
}

// ---------------------------------------------------------------------------
// MMA flash attention, 64-query tile, 4 warps, cp.async 2-stage pipeline.
// ---------------------------------------------------------------------------
#define AT_KHI     0
#define AT_KLO     9216
#define AT_VHI     18432
#define AT_VLO     27648
#define AT_BIAS    36864
#define AT_STAGE_B 54272               // 36864 + 64*68*4
#define AT_SMEM    (2 * AT_STAGE_B)    // 108544 bytes

__device__ __forceinline__ void attn_issue(
    uint32_t sb, int nh, int i0, int j0, int lr, int lc2,
    const unsigned short* __restrict__ Khi, const unsigned short* __restrict__ Klo,
    const unsigned short* __restrict__ Vthi, const unsigned short* __restrict__ Vtlo,
    const float* __restrict__ QE)
{
    const size_t krow = ((size_t)(nh * SEQL + j0 + lr)) * 64 + lc2;
    const size_t vrow = ((size_t)(nh * 64 + lr)) * SEQL + j0 + lc2;
    const uint32_t so = (uint32_t)(lr * 72 + lc2) * 2;
    #pragma unroll
    for (int u = 0; u < 4; u++) {
        cp16(sb + AT_KHI + so + u * 16, Khi + krow + u * 8);
        cp16(sb + AT_KLO + so + u * 16, Klo + krow + u * 8);
        cp16(sb + AT_VHI + so + u * 16, Vthi + vrow + u * 8);
        cp16(sb + AT_VLO + so + u * 16, Vtlo + vrow + u * 8);
    }
    const float* gb = QE + (size_t)(nh * SEQL + i0 + lr) * SEQL + j0 + lc2;
    const uint32_t sbia = sb + AT_BIAS + (uint32_t)(lr * 68 + lc2) * 4;
    #pragma unroll
    for (int u = 0; u < 8; u++)
        cp16(sbia + u * 16, gb + u * 4);
}

__global__ __launch_bounds__(128) void ra_attn_mma(
    const unsigned short* __restrict__ Qhi, const unsigned short* __restrict__ Qlo,
    const unsigned short* __restrict__ Khi, const unsigned short* __restrict__ Klo,
    const unsigned short* __restrict__ Vthi, const unsigned short* __restrict__ Vtlo,
    const float* __restrict__ QE,
    unsigned short* __restrict__ AOhi, unsigned short* __restrict__ AOlo)
{
    extern __shared__ char smc[];
    const uint32_t smb = smem_u32(smc);
    const int nh = blockIdx.y;
    const int i0 = (int)(gridDim.x - 1 - blockIdx.x) * 64;   // big tiles first
    const int t = threadIdx.x;
    const int w = t >> 5, lane = t & 31;
    const int g = lane >> 2, q4 = lane & 3;
    const int lr = t >> 1, lc2 = (t & 1) * 32;
    const int lrow16 = lane & 15, lcol8 = (lane >> 4) << 3;
    const int ntj = i0 >> 6;

    // kick off prefetch of tile 0 into stage 0 (async)
    attn_issue(smb, nh, i0, 0, lr, lc2, Khi, Klo, Vthi, Vtlo, QE);
    cp_commit();

    // ---- Q fragments via staging in stage-1 KHI region (free until c=1) ----
    uint32_t qh[4][4], ql[4][4];
    {
        const uint4* src = (const uint4*)(Qhi + ((size_t)(nh * SEQL + i0 + lr)) * 64 + lc2);
        uint4* dst = (uint4*)(smc + AT_STAGE_B + (lr * 72 + lc2) * 2);
        #pragma unroll
        for (int u = 0; u < 4; u++) dst[u] = src[u];
    }
    __syncthreads();
    #pragma unroll
    for (int kt = 0; kt < 4; kt++)
        ldsm4(smb + AT_STAGE_B + (uint32_t)((16 * w + lrow16) * 72 + kt * 16 + lcol8) * 2,
              qh[kt][0], qh[kt][1], qh[kt][2], qh[kt][3]);
    __syncthreads();
    {
        const uint4* src = (const uint4*)(Qlo + ((size_t)(nh * SEQL + i0 + lr)) * 64 + lc2);
        uint4* dst = (uint4*)(smc + AT_STAGE_B + (lr * 72 + lc2) * 2);
        #pragma unroll
        for (int u = 0; u < 4; u++) dst[u] = src[u];
    }
    __syncthreads();
    #pragma unroll
    for (int kt = 0; kt < 4; kt++)
        ldsm4(smb + AT_STAGE_B + (uint32_t)((16 * w + lrow16) * 72 + kt * 16 + lcol8) * 2,
              ql[kt][0], ql[kt][1], ql[kt][2], ql[kt][3]);
    __syncthreads();

    float o[8][4];
    #pragma unroll
    for (int nt = 0; nt < 8; nt++)
        #pragma unroll
        for (int i = 0; i < 4; i++) o[nt][i] = 0.f;
    float rm[2] = {-1e30f, -1e30f};
    float rl[2] = {0.f, 0.f};

    for (int c = 0; c <= ntj; c++) {
        if (c < ntj) {
            attn_issue(smb + (uint32_t)(((c + 1) & 1) * AT_STAGE_B),
                       nh, i0, (c + 1) * 64, lr, lc2, Khi, Klo, Vthi, Vtlo, QE);
            cp_commit();
            cp_wait<1>();
        } else {
            cp_wait<0>();
        }
        __syncthreads();

        const uint32_t stg = smb + (uint32_t)((c & 1) * AT_STAGE_B);
        const char* stgc = smc + (size_t)((c & 1) * AT_STAGE_B);

        // ---- S = QK^T (3-term split) ----
        float s[8][4];
        #pragma unroll
        for (int nt = 0; nt < 8; nt++)
            #pragma unroll
            for (int i = 0; i < 4; i++) s[nt][i] = 0.f;
        #pragma unroll
        for (int kt = 0; kt < 4; kt++) {
            uint32_t kbh[8][2], kbl[8][2];
            #pragma unroll
            for (int grp = 0; grp < 4; grp++) {
                const uint32_t off = (uint32_t)((grp * 16 + lrow16) * 72 + kt * 16 + lcol8) * 2;
                uint32_t r0, r1, r2, r3;
                ldsm4(stg + AT_KHI + off, r0, r1, r2, r3);
                kbh[grp * 2][0] = r0; kbh[grp * 2][1] = r2;
                kbh[grp * 2 + 1][0] = r1; kbh[grp * 2 + 1][1] = r3;
                ldsm4(stg + AT_KLO + off, r0, r1, r2, r3);
                kbl[grp * 2][0] = r0; kbl[grp * 2][1] = r2;
                kbl[grp * 2 + 1][0] = r1; kbl[grp * 2 + 1][1] = r3;
            }
            #pragma unroll
            for (int nt = 0; nt < 8; nt++) {
                MMA_BF16(s[nt], qh[kt], kbh[nt]);
                MMA_BF16(s[nt], qh[kt], kbl[nt]);
                MMA_BF16(s[nt], ql[kt], kbh[nt]);
            }
        }

        // ---- bias + causal mask ----
        const int r0l = 16 * w + g, r1l = r0l + 8;
        #pragma unroll
        for (int nt = 0; nt < 8; nt++) {
            const int cl = nt * 8 + q4 * 2;
            const float2 b0 = *(const float2*)(stgc + AT_BIAS + (r0l * 68 + cl) * 4);
            const float2 b1 = *(const float2*)(stgc + AT_BIAS + (r1l * 68 + cl) * 4);
            s[nt][0] += b0.x; s[nt][1] += b0.y;
            s[nt][2] += b1.x; s[nt][3] += b1.y;
        }
        if (c == ntj) {
            #pragma unroll
            for (int nt = 0; nt < 8; nt++) {
                const int cl = nt * 8 + q4 * 2;
                if (cl     > r0l) s[nt][0] = -1e30f;
                if (cl + 1 > r0l) s[nt][1] = -1e30f;
                if (cl     > r1l) s[nt][2] = -1e30f;
                if (cl + 1 > r1l) s[nt][3] = -1e30f;
            }
        }

        // ---- online softmax ----
        float mx0 = -1e30f, mx1 = -1e30f;
        #pragma unroll
        for (int nt = 0; nt < 8; nt++) {
            mx0 = fmaxf(mx0, fmaxf(s[nt][0], s[nt][1]));
            mx1 = fmaxf(mx1, fmaxf(s[nt][2], s[nt][3]));
        }
        mx0 = fmaxf(mx0, __shfl_xor_sync(0xffffffffu, mx0, 1));
        mx0 = fmaxf(mx0, __shfl_xor_sync(0xffffffffu, mx0, 2));
        mx1 = fmaxf(mx1, __shfl_xor_sync(0xffffffffu, mx1, 1));
        mx1 = fmaxf(mx1, __shfl_xor_sync(0xffffffffu, mx1, 2));
        const float m0n = fmaxf(rm[0], mx0);
        const float m1n = fmaxf(rm[1], mx1);
        const float a0 = __expf(rm[0] - m0n);
        const float a1 = __expf(rm[1] - m1n);
        float ps0 = 0.f, ps1 = 0.f;
        uint32_t ph[4][4], pl[4][4];
        #pragma unroll
        for (int nt = 0; nt < 8; nt++) {
            const float p0 = __expf(s[nt][0] - m0n);
            const float p1 = __expf(s[nt][1] - m0n);
            const float p2 = __expf(s[nt][2] - m1n);
            const float p3 = __expf(s[nt][3] - m1n);
            ps0 += p0 + p1; ps1 += p2 + p3;
            const int kt = nt >> 1, sl = (nt & 1) * 2;
            const uint32_t hp01 = packbf(p0, p1);
            const uint32_t hp23 = packbf(p2, p3);
            ph[kt][sl + 0] = hp01;
            ph[kt][sl + 1] = hp23;
            pl[kt][sl + 0] = packbf(p0 - __uint_as_float(hp01 << 16),
                                    p1 - __uint_as_float(hp01 & 0xffff0000u));
            pl[kt][sl + 1] = packbf(p2 - __uint_as_float(hp23 << 16),
                                    p3 - __uint_as_float(hp23 & 0xffff0000u));
        }
        ps0 += __shfl_xor_sync(0xffffffffu, ps0, 1);
        ps0 += __shfl_xor_sync(0xffffffffu, ps0, 2);
        ps1 += __shfl_xor_sync(0xffffffffu, ps1, 1);
        ps1 += __shfl_xor_sync(0xffffffffu, ps1, 2);
        rl[0] = rl[0] * a0 + ps0;
        rl[1] = rl[1] * a1 + ps1;
        rm[0] = m0n; rm[1] = m1n;
        #pragma unroll
        for (int nt = 0; nt < 8; nt++) {
            o[nt][0] *= a0; o[nt][1] *= a0;
            o[nt][2] *= a1; o[nt][3] *= a1;
        }

        // ---- O += P @ V (3-term split) ----
        #pragma unroll
        for (int kt = 0; kt < 4; kt++) {
            uint32_t vbh[8][2], vbl[8][2];
            #pragma unroll
            for (int grp = 0; grp < 4; grp++) {
                const uint32_t off = (uint32_t)((grp * 16 + lrow16) * 72 + kt * 16 + lcol8) * 2;
                uint32_t r0, r1, r2, r3;
                ldsm4(stg + AT_VHI + off, r0, r1, r2, r3);
                vbh[grp * 2][0] = r0; vbh[grp * 2][1] = r2;
                vbh[grp * 2 + 1][0] = r1; vbh[grp * 2 + 1][1] = r3;
                ldsm4(stg + AT_VLO + off, r0, r1, r2, r3);
                vbl[grp * 2][0] = r0; vbl[grp * 2][1] = r2;
                vbl[grp * 2 + 1][0] = r1; vbl[grp * 2 + 1][1] = r3;
            }
            #pragma unroll
            for (int nt = 0; nt < 8; nt++) {
                MMA_BF16(o[nt], ph[kt], vbh[nt]);
                MMA_BF16(o[nt], ph[kt], vbl[nt]);
                MMA_BF16(o[nt], pl[kt], vbh[nt]);
            }
        }
        __syncthreads();
    }

    // ---- epilogue: normalize, split, write AO hi/lo (natural layout) ----
    const float inv0 = 1.f / rl[0], inv1 = 1.f / rl[1];
    const int n = nh >> 4, h = nh & (NHEADS - 1);
    const int r0g = i0 + 16 * w + g, r1g = r0g + 8;
    #pragma unroll
    for (int nt = 0; nt < 8; nt++) {
        const int col = h * 64 + nt * 8 + q4 * 2;
        const float v0 = o[nt][0] * inv0, v1 = o[nt][1] * inv0;
        const float v2 = o[nt][2] * inv1, v3 = o[nt][3] * inv1;
        const size_t idx0 = ((size_t)(n * SEQL + r0g)) * DMODEL + col;
        const size_t idx1 = ((size_t)(n * SEQL + r1g)) * DMODEL + col;
        const uint32_t hp01 = packbf(v0, v1);
        const uint32_t hp23 = packbf(v2, v3);
        *(uint32_t*)(AOhi + idx0) = hp01;
        *(uint32_t*)(AOhi + idx1) = hp23;
        *(uint32_t*)(AOlo + idx0) = packbf(v0 - __uint_as_float(hp01 << 16),
                                           v1 - __uint_as_float(hp01 & 0xffff0000u));
        *(uint32_t*)(AOlo + idx1) = packbf(v2 - __uint_as_float(hp23 << 16),
                                           v3 - __uint_as_float(hp23 & 0xffff0000u));
    }
}

// ---------------------------------------------------------------------------
extern "C" void kernel_launch(void* const* d_in, const int* in_sizes, int n_in,
                              void* d_out, int out_size)
{
    (void)in_sizes; (void)n_in; (void)out_size;
    const float* q_in    = (const float*)d_in[0];
    const float* k_in    = (const float*)d_in[1];
    const float* v_in    = (const float*)d_in[2];
    /* d_in[3] = mask (triu k=1) — handled analytically */
    const float* Wq      = (const float*)d_in[4];
    const float* bq      = (const float*)d_in[5];
    const float* Wk      = (const float*)d_in[6];
    const float* bk      = (const float*)d_in[7];
    const float* Wv      = (const float*)d_in[8];
    const float* bv      = (const float*)d_in[9];
    const float* Wo      = (const float*)d_in[10];
    const float* bo      = (const float*)d_in[11];
    const float* pos_emb = (const float*)d_in[12];

    float *QEp, *zb;
    unsigned short (*Xh)[NLROWS * DMODEL], (*Xl)[NLROWS * DMODEL];
    unsigned short (*Bh)[DMODEL * DMODEL], (*Bl)[DMODEL * DMODEL];
    unsigned short *Eh, *El, *Qh, *Ql, *Kh, *Kl, *Vh, *Vl, *Vth, *Vtl;
    cudaGetSymbolAddress((void**)&QEp, g_QE);
    cudaGetSymbolAddress((void**)&zb,  g_zbias);
    cudaGetSymbolAddress((void**)&Xh,  g_Xhi);
    cudaGetSymbolAddress((void**)&Xl,  g_Xlo);
    cudaGetSymbolAddress((void**)&Bh,  g_Bhi);
    cudaGetSymbolAddress((void**)&Bl,  g_Blo);
    cudaGetSymbolAddress((void**)&Eh,  g_Ehi);
    cudaGetSymbolAddress((void**)&El,  g_Elo);
    cudaGetSymbolAddress((void**)&Qh,  g_Qhi);
    cudaGetSymbolAddress((void**)&Ql,  g_Qlo);
    cudaGetSymbolAddress((void**)&Kh,  g_Khi);
    cudaGetSymbolAddress((void**)&Kl,  g_Klo);
    cudaGetSymbolAddress((void**)&Vh,  g_Vhi);
    cudaGetSymbolAddress((void**)&Vl,  g_Vlo);
    cudaGetSymbolAddress((void**)&Vth, g_Vthi);
    cudaGetSymbolAddress((void**)&Vtl, g_Vtlo);

    cudaFuncSetAttribute(ra_mma_gemm, cudaFuncAttributeMaxDynamicSharedMemorySize,
                         SMEM_DYN);
    cudaFuncSetAttribute(ra_attn_mma, cudaFuncAttributeMaxDynamicSharedMemorySize,
                         AT_SMEM);

    const dim3 gproj(DMODEL / 128, NLROWS / 128);  // (8, 32)
    const int  n4x = (NLROWS * DMODEL) / 4;

    // All conversions up front (fused launches)
    ra_conv_hilo3<<<dim3(n4x / 256, 3), 256>>>(q_in, k_in, v_in,
                                               Xh[0], Xl[0], Xh[1], Xl[1],
                                               Xh[2], Xl[2], n4x);
    ra_conv_wt4<<<dim3(32, 32, 4), dim3(32, 8)>>>(Wq, Wk, Wv, Wo,
                                                  Bh[0], Bl[0], Bh[1], Bl[1],
                                                  Bh[2], Bl[2], Bh[3], Bl[3]);
    ra_conv_hilo<<<(SEQL * DEPTH / 4) / 256, 256>>>(pos_emb + SEQL * DEPTH,
                                                    Eh, El, SEQL * DEPTH / 4);

    // Projections (Q carries 1/sqrt(d))
    ra_mma_gemm<<<gproj, 256, SMEM_DYN>>>(Xh[0], Xl[0], Bh[0], Bl[0], bq,
                                          nullptr, Qh, Ql, DMODEL, 0.125f, 1);
    ra_mma_gemm<<<gproj, 256, SMEM_DYN>>>(Xh[1], Xl[1], Bh[1], Bl[1], bk,
                                          nullptr, Kh, Kl, DMODEL, 1.0f, 1);
    ra_mma_gemm<<<gproj, 256, SMEM_DYN>>>(Xh[2], Xl[2], Bh[2], Bl[2], bv,
                                          nullptr, Vh, Vl, DMODEL, 1.0f, 1);
    ra_vt<<<dim3(16, NHTOT), 128>>>(Vh, Vl, Vth, Vtl);

    // QE = Q @ E^T (K=64), diag-shifted band
    ra_mma_gemm<<<dim3(SEQL / 128, QROWS / 128), 256, SMEM_DYN>>>(
        Qh, Ql, Eh, El, zb, QEp, nullptr, nullptr, DEPTH, 1.0f, 2);

    // Pipelined MMA flash attention -> AO hi/lo (reuses X[0])
    ra_attn_mma<<<dim3(SEQL / 64, NHTOT), 128, AT_SMEM>>>(
        Qh, Ql, Kh, Kl, Vth, Vtl, QEp, Xh[0], Xl[0]);

    // Output projection -> f32 d_out
    ra_mma_gemm<<<gproj, 256, SMEM_DYN>>>(Xh[0], Xl[0], Bh[3], Bl[3], bo,
                                          (float*)d_out, nullptr, nullptr,
                                          DMODEL, 1.0f, 0);
}